// round 9
// baseline (speedup 1.0000x reference)
#include <cuda_runtime.h>
#include <cuda_fp16.h>
#include <math.h>
#include <stdint.h>

// ---------------- problem constants ----------------
#define NS   4000
#define SL   128
#define VEC  50
#define PDIM 5
#define EMB  60
#define HID  230
#define NBAG 500
#define NREL 25

#define NPC2 240          // channels padded to 30 n-tiles (ldsm4 pairs)
#define KT   192          // K = 3 taps * 64
#define GRID_ENC 304      // 2 CTAs per SM

// smem offsets (base 128-aligned)
#define OFF_B    0u             // 240*384 = 92160
#define OFF_AH   92160u         // 130 rows * 128B = 16640
#define OFF_SCR  108800u        // 2*240*4 = 1920
#define SMEM_NEED (110720 + 128)

__device__ float g_h[NS * HID];
__device__ __half g_B[NPC2 * KT];

// ---------------- helpers ----------------
__device__ __forceinline__ uint32_t smem_u32(const void* p) {
    uint32_t a;
    asm("{ .reg .u64 t; cvta.to.shared.u64 t, %1; cvt.u32.u64 %0, t; }"
        : "=r"(a) : "l"(p));
    return a;
}
__device__ __forceinline__ void sts32(uint32_t a, uint32_t v) {
    asm volatile("st.shared.u32 [%0], %1;" :: "r"(a), "r"(v));
}
__device__ __forceinline__ void sts64(uint32_t a, uint2 v) {
    asm volatile("st.shared.v2.u32 [%0], {%1,%2};" :: "r"(a), "r"(v.x), "r"(v.y));
}
__device__ __forceinline__ void sts128z(uint32_t a) {
    asm volatile("st.shared.v4.u32 [%0], {%1,%1,%1,%1};" :: "r"(a), "r"(0u));
}
__device__ __forceinline__ void ldsm4(uint32_t& r0, uint32_t& r1, uint32_t& r2,
                                      uint32_t& r3, uint32_t addr) {
    asm volatile("ldmatrix.sync.aligned.m8n8.x4.shared.b16 {%0,%1,%2,%3}, [%4];"
                 : "=r"(r0), "=r"(r1), "=r"(r2), "=r"(r3) : "r"(addr));
}
__device__ __forceinline__ void mma16816(float* c, const uint32_t* a,
                                         uint32_t b0, uint32_t b1) {
    asm volatile(
        "mma.sync.aligned.m16n8k16.row.col.f32.f16.f16.f32 "
        "{%0,%1,%2,%3}, {%4,%5,%6,%7}, {%8,%9}, {%0,%1,%2,%3};"
        : "+f"(c[0]), "+f"(c[1]), "+f"(c[2]), "+f"(c[3])
        : "r"(a[0]), "r"(a[1]), "r"(a[2]), "r"(a[3]), "r"(b0), "r"(b1));
}

// ---------------- kernel 0: conv_w -> fp16 im2col [c][tap*64+e] -------------
__global__ void prepB(const float* __restrict__ conv_w) {
    int idx = blockIdx.x * blockDim.x + threadIdx.x;
    if (idx >= NPC2 * KT) return;
    int c = idx / KT, k = idx - c * KT;
    int tap = k >> 6, e = k & 63;
    float v = 0.f;
    if (c < HID && e < EMB) v = conv_w[(c * EMB + e) * 3 + tap];
    g_B[idx] = __float2half_rn(v);
}

// ---------------- kernel 1: persistent mma.sync encoder ---------------------
// Single-term fp16: D = A_fp16 * B_fp16^T, fp32 accum. Single 130-row A slab;
// taps realized by shifted ldmatrix row bases. 2 CTAs/SM for phase overlap.
// Warp (msplit = wid>>2, nsplit = wid&3): rows [64*msplit, +64) x n-tiles
// [8*nsplit, +8) (last split 6 tiles).
__global__ void __launch_bounds__(256, 2) enc_kernel(
    const int* __restrict__ X, const int* __restrict__ pos1,
    const int* __restrict__ pos2,
    const float* __restrict__ word_emb, const float* __restrict__ p1e,
    const float* __restrict__ p2e, const float* __restrict__ conv_b)
{
    extern __shared__ char sm_raw[];
    const uint32_t raw  = smem_u32(sm_raw);
    const uint32_t base = (raw + 127u) & ~127u;
    float* scr = (float*)(sm_raw + (base - raw) + OFF_SCR);

    const int tid  = threadIdx.x;
    const int wid  = tid >> 5;
    const int lane = tid & 31;

    // ---- stage resident B, swizzled rows of 384B
    for (int t = tid; t < NPC2 * KT / 4; t += 256) {
        int idx = t * 4;
        int c = idx / KT, k = idx - c * KT;
        uint32_t off = (uint32_t)c * 384u
                     + (((uint32_t)k * 2u) ^ (((uint32_t)(c & 7)) << 4));
        sts64(base + OFF_B + off, *reinterpret_cast<const uint2*>(g_B + idx));
    }
    // ---- zero A slab ONCE (pads persist; data rows overwritten per sentence)
    for (int t = tid; t < 16640 / 16; t += 256)
        sts128z(base + OFF_AH + (uint32_t)t * 16u);
    __syncthreads();

    // ---- per-warp tiling
    const int msplit = wid >> 2;            // 0/1 -> rows [64*msplit, +64)
    const int nsplit = wid & 3;
    const int nt0    = nsplit * 8;
    const int ntn    = (nsplit < 3) ? 8 : 6;
    const int npair  = ntn >> 1;

    // ldmatrix lane addressing
    const uint32_t lrow = (uint32_t)((lane & 7) + ((lane >> 3) & 1) * 8);
    const uint32_t lkb  = ((uint32_t)(lane >> 4) & 1u) * 16u;
    const uint32_t brow = (uint32_t)((lane & 7) + ((lane >> 4) & 1) * 8);
    const uint32_t bkb  = ((uint32_t)(lane >> 3) & 1u) * 16u;

    for (int n = blockIdx.x; n < NS; n += GRID_ENC) {
        // ================= build A (fp16, one slab) =================
        for (int idx = tid; idx < SL * 30; idx += 256) {
            int l = idx / 30, ep = idx - l * 30;
            int e0 = ep * 2;
            float x0, x1;
            if (e0 <= VEC - 2) {                         // word pairs
                int tok = X[n * SL + l];
                float2 w = *reinterpret_cast<const float2*>(word_emb + tok * VEC + e0);
                x0 = w.x; x1 = w.y;
            } else if (e0 < 54) {                        // p1 pairs
                int tok = pos1[n * SL + l];
                x0 = p1e[tok * PDIM + (e0 - 50)];
                x1 = p1e[tok * PDIM + (e0 - 49)];
            } else if (e0 == 54) {                       // boundary (p1[4], p2[0])
                x0 = p1e[pos1[n * SL + l] * PDIM + 4];
                x1 = p2e[pos2[n * SL + l] * PDIM + 0];
            } else {                                     // p2 pairs
                int tok = pos2[n * SL + l];
                x0 = p2e[tok * PDIM + (e0 - 55)];
                x1 = p2e[tok * PDIM + (e0 - 54)];
            }
            __half h0 = __float2half_rn(x0);
            __half h1 = __float2half_rn(x1);
            uint32_t uh = (uint32_t)__half_as_ushort(h0)
                        | ((uint32_t)__half_as_ushort(h1) << 16);
            uint32_t p   = (uint32_t)(l + 1);
            uint32_t off = p * 128u + (((uint32_t)e0 * 2u) ^ ((p & 7u) << 4));
            sts32(base + OFF_AH + off, uh);
        }
        __syncthreads();

        // ================= MMA phase (single term) =================
        float acc[4][8][4];
        #pragma unroll
        for (int mb = 0; mb < 4; mb++)
            #pragma unroll
            for (int nt = 0; nt < 8; nt++)
                #pragma unroll
                for (int q = 0; q < 4; q++) acc[mb][nt][q] = 0.f;

        for (int t = 0; t < 3; t++) {
            #pragma unroll
            for (int ks = 0; ks < 4; ks++) {
                uint32_t bh[4][4];
                const uint32_t kbB = (uint32_t)(t * 128 + ks * 32) + bkb;
                #pragma unroll
                for (int pp = 0; pp < 4; pp++) {
                    if (pp < npair) {
                        uint32_t c = (uint32_t)(nt0 + 2 * pp) * 8u + brow;
                        uint32_t off = c * 384u + (kbB ^ ((c & 7u) << 4));
                        ldsm4(bh[pp][0], bh[pp][1], bh[pp][2], bh[pp][3],
                              base + OFF_B + off);
                    }
                }
                const uint32_t kbA = (uint32_t)(ks * 32) + lkb;
                #pragma unroll
                for (int mb = 0; mb < 4; mb++) {
                    uint32_t r = (uint32_t)(msplit * 64 + mb * 16 + t) + lrow;
                    uint32_t aoff = r * 128u + (kbA ^ ((r & 7u) << 4));
                    uint32_t ah[4];
                    ldsm4(ah[0], ah[1], ah[2], ah[3], base + OFF_AH + aoff);
                    #pragma unroll
                    for (int nt = 0; nt < 8; nt++) {
                        if (nt < ntn) {
                            int pp = nt >> 1, hf = (nt & 1) * 2;
                            mma16816(acc[mb][nt], ah, bh[pp][hf], bh[pp][hf + 1]);
                        }
                    }
                }
            }
        }

        // ================= epilogue: max over positions =================
        #pragma unroll
        for (int nt = 0; nt < 8; nt++) {
            if (nt < ntn) {
                float ve = -1e30f, vo = -1e30f;
                #pragma unroll
                for (int mb = 0; mb < 4; mb++) {
                    ve = fmaxf(ve, fmaxf(acc[mb][nt][0], acc[mb][nt][2]));
                    vo = fmaxf(vo, fmaxf(acc[mb][nt][1], acc[mb][nt][3]));
                }
                #pragma unroll
                for (int o = 4; o <= 16; o <<= 1) {
                    ve = fmaxf(ve, __shfl_xor_sync(0xffffffffu, ve, o));
                    vo = fmaxf(vo, __shfl_xor_sync(0xffffffffu, vo, o));
                }
                if (lane < 4) {
                    int col = (nt0 + nt) * 8 + 2 * lane;
                    scr[msplit * NPC2 + col]     = ve;
                    scr[msplit * NPC2 + col + 1] = vo;
                }
            }
        }
        __syncthreads();
        if (tid < HID) {
            float m  = fmaxf(scr[tid], scr[NPC2 + tid]);
            float hv = m + conv_b[tid];
            g_h[n * HID + tid] = hv > 0.f ? hv : 0.f;
        }
        __syncthreads();
    }
}

// ---------------- kernel 2: bag attention + classifier ----------------
__global__ void __launch_bounds__(256) bag_kernel(
    const int* __restrict__ scope, const int* __restrict__ relation,
    const float* __restrict__ rel_w, const float* __restrict__ rel_b,
    float* __restrict__ out)
{
    __shared__ float rq[HID];
    __shared__ float rep[HID];
    __shared__ float logits[64];
    __shared__ float alpha[64];

    const int b = blockIdx.x, tid = threadIdx.x;
    const int wid = tid >> 5, lane = tid & 31;
    const int s0 = scope[2 * b], s1 = scope[2 * b + 1];
    const int sz = s1 - s0;
    const int rel = relation[b];

    for (int d = tid; d < HID; d += 256) rq[d] = rel_w[rel * HID + d];
    __syncthreads();

    for (int i = wid; i < sz && i < 64; i += 8) {
        const float* hr = g_h + (s0 + i) * HID;
        float s = 0.f;
        for (int d = lane; d < HID; d += 32) s += hr[d] * rq[d];
        #pragma unroll
        for (int o = 16; o > 0; o >>= 1) s += __shfl_xor_sync(0xffffffffu, s, o);
        if (lane == 0) logits[i] = s;
    }
    __syncthreads();

    if (tid == 0) {
        float m = -1e30f;
        for (int i = 0; i < sz && i < 64; i++) m = fmaxf(m, logits[i]);
        float den = 0.f;
        for (int i = 0; i < sz && i < 64; i++) {
            float e = expf(logits[i] - m);
            alpha[i] = e; den += e;
        }
        float inv = 1.f / den;
        for (int i = 0; i < sz && i < 64; i++) alpha[i] *= inv;
    }
    __syncthreads();

    for (int d = tid; d < HID; d += 256) {
        float a = 0.f;
        for (int i = 0; i < sz && i < 64; i++)
            a += alpha[i] * g_h[(s0 + i) * HID + d];
        rep[d] = a;
    }
    __syncthreads();

    for (int r = wid; r < NREL; r += 8) {
        float s = 0.f;
        for (int d = lane; d < HID; d += 32) s += rep[d] * rel_w[r * HID + d];
        #pragma unroll
        for (int o = 16; o > 0; o >>= 1) s += __shfl_xor_sync(0xffffffffu, s, o);
        if (lane == 0) out[b * NREL + r] = s + rel_b[r];
    }
}

// ---------------------------------------------------------------------------
extern "C" void kernel_launch(void* const* d_in, const int* in_sizes, int n_in,
                              void* d_out, int out_size)
{
    const int*   X        = (const int*)d_in[0];
    const int*   pos1     = (const int*)d_in[1];
    const int*   pos2     = (const int*)d_in[2];
    const int*   scope    = (const int*)d_in[5];
    const int*   relation = (const int*)d_in[6];
    const float* word_emb = (const float*)d_in[7];
    const float* p1e      = (const float*)d_in[8];
    const float* p2e      = (const float*)d_in[9];
    const float* conv_w   = (const float*)d_in[10];
    const float* conv_b   = (const float*)d_in[11];
    const float* rel_w    = (const float*)d_in[12];
    const float* rel_b    = (const float*)d_in[13];
    float*       out      = (float*)d_out;

    cudaFuncSetAttribute(enc_kernel,
                         cudaFuncAttributeMaxDynamicSharedMemorySize, SMEM_NEED);

    prepB<<<(NPC2 * KT + 255) / 256, 256>>>(conv_w);
    enc_kernel<<<GRID_ENC, 256, SMEM_NEED>>>(X, pos1, pos2, word_emb, p1e, p2e,
                                             conv_b);
    bag_kernel<<<NBAG, 256>>>(scope, relation, rel_w, rel_b, out);
}

// round 10
// speedup vs baseline: 1.5844x; 1.5844x over previous
#include <cuda_runtime.h>
#include <cuda_fp16.h>
#include <math.h>
#include <stdint.h>

// ---------------- problem constants ----------------
#define NS   4000
#define SL   128
#define VEC  50
#define PDIM 5
#define EMB  60
#define HID  230
#define NBAG 500
#define NREL 25

#define NPC2 240          // channels padded to 30 n-tiles (ldsm4 pairs)
#define KT   192          // K = 3 taps * 64
#define GRID_ENC 152      // 1 CTA per SM (crossbar-bound: no co-residency)

// smem offsets (base 128-aligned)
#define OFF_B    0u             // 240*384 = 92160
#define OFF_AH   92160u         // 130 rows * 128B = 16640
#define OFF_SCR  108800u        // 2*240*4 = 1920
#define SMEM_NEED (110720 + 128)

__device__ float g_h[NS * HID];
__device__ __half g_B[NPC2 * KT];

// ---------------- helpers ----------------
__device__ __forceinline__ uint32_t smem_u32(const void* p) {
    uint32_t a;
    asm("{ .reg .u64 t; cvta.to.shared.u64 t, %1; cvt.u32.u64 %0, t; }"
        : "=r"(a) : "l"(p));
    return a;
}
__device__ __forceinline__ void sts32(uint32_t a, uint32_t v) {
    asm volatile("st.shared.u32 [%0], %1;" :: "r"(a), "r"(v));
}
__device__ __forceinline__ void sts64(uint32_t a, uint2 v) {
    asm volatile("st.shared.v2.u32 [%0], {%1,%2};" :: "r"(a), "r"(v.x), "r"(v.y));
}
__device__ __forceinline__ void sts128z(uint32_t a) {
    asm volatile("st.shared.v4.u32 [%0], {%1,%1,%1,%1};" :: "r"(a), "r"(0u));
}
__device__ __forceinline__ void ldsm4(uint32_t& r0, uint32_t& r1, uint32_t& r2,
                                      uint32_t& r3, uint32_t addr) {
    asm volatile("ldmatrix.sync.aligned.m8n8.x4.shared.b16 {%0,%1,%2,%3}, [%4];"
                 : "=r"(r0), "=r"(r1), "=r"(r2), "=r"(r3) : "r"(addr));
}
__device__ __forceinline__ void mma16816(float* c, const uint32_t* a,
                                         uint32_t b0, uint32_t b1) {
    asm volatile(
        "mma.sync.aligned.m16n8k16.row.col.f32.f16.f16.f32 "
        "{%0,%1,%2,%3}, {%4,%5,%6,%7}, {%8,%9}, {%0,%1,%2,%3};"
        : "+f"(c[0]), "+f"(c[1]), "+f"(c[2]), "+f"(c[3])
        : "r"(a[0]), "r"(a[1]), "r"(a[2]), "r"(a[3]), "r"(b0), "r"(b1));
}

// ---------------- kernel 0: conv_w -> fp16 im2col [c][tap*64+e] -------------
__global__ void prepB(const float* __restrict__ conv_w) {
    int idx = blockIdx.x * blockDim.x + threadIdx.x;
    if (idx >= NPC2 * KT) return;
    int c = idx / KT, k = idx - c * KT;
    int tap = k >> 6, e = k & 63;
    float v = 0.f;
    if (c < HID && e < EMB) v = conv_w[(c * EMB + e) * 3 + tap];
    g_B[idx] = __float2half_rn(v);
}

// ---------------- kernel 1: persistent mma.sync encoder ---------------------
// Single-term fp16: D = A_fp16 * B_fp16^T, fp32 accum. Single 130-row A slab;
// taps realized by shifted ldmatrix row bases. 1 CTA/SM (smem-crossbar bound).
// Warp (msplit = wid>>2, nsplit = wid&3): rows [64*msplit, +64) x n-tiles
// [8*nsplit, +8) (last split 6 tiles).
__global__ void __launch_bounds__(256, 1) enc_kernel(
    const int* __restrict__ X, const int* __restrict__ pos1,
    const int* __restrict__ pos2,
    const float* __restrict__ word_emb, const float* __restrict__ p1e,
    const float* __restrict__ p2e, const float* __restrict__ conv_b)
{
    extern __shared__ char sm_raw[];
    const uint32_t raw  = smem_u32(sm_raw);
    const uint32_t base = (raw + 127u) & ~127u;
    float* scr = (float*)(sm_raw + (base - raw) + OFF_SCR);

    const int tid  = threadIdx.x;
    const int wid  = tid >> 5;
    const int lane = tid & 31;

    // ---- stage resident B, swizzled rows of 384B
    for (int t = tid; t < NPC2 * KT / 4; t += 256) {
        int idx = t * 4;
        int c = idx / KT, k = idx - c * KT;
        uint32_t off = (uint32_t)c * 384u
                     + (((uint32_t)k * 2u) ^ (((uint32_t)(c & 7)) << 4));
        sts64(base + OFF_B + off, *reinterpret_cast<const uint2*>(g_B + idx));
    }
    // ---- zero A slab ONCE (pads persist; data rows overwritten per sentence)
    for (int t = tid; t < 16640 / 16; t += 256)
        sts128z(base + OFF_AH + (uint32_t)t * 16u);
    __syncthreads();

    // ---- per-warp tiling
    const int msplit = wid >> 2;            // 0/1 -> rows [64*msplit, +64)
    const int nsplit = wid & 3;
    const int nt0    = nsplit * 8;
    const int ntn    = (nsplit < 3) ? 8 : 6;
    const int npair  = ntn >> 1;

    // ldmatrix lane addressing
    const uint32_t lrow = (uint32_t)((lane & 7) + ((lane >> 3) & 1) * 8);
    const uint32_t lkb  = ((uint32_t)(lane >> 4) & 1u) * 16u;
    const uint32_t brow = (uint32_t)((lane & 7) + ((lane >> 4) & 1) * 8);
    const uint32_t bkb  = ((uint32_t)(lane >> 3) & 1u) * 16u;

    for (int n = blockIdx.x; n < NS; n += GRID_ENC) {
        // ================= build A (fp16, one slab) =================
        for (int idx = tid; idx < SL * 30; idx += 256) {
            int l = idx / 30, ep = idx - l * 30;
            int e0 = ep * 2;
            float x0, x1;
            if (e0 <= VEC - 2) {                         // word pairs
                int tok = X[n * SL + l];
                float2 w = *reinterpret_cast<const float2*>(word_emb + tok * VEC + e0);
                x0 = w.x; x1 = w.y;
            } else if (e0 < 54) {                        // p1 pairs
                int tok = pos1[n * SL + l];
                x0 = p1e[tok * PDIM + (e0 - 50)];
                x1 = p1e[tok * PDIM + (e0 - 49)];
            } else if (e0 == 54) {                       // boundary (p1[4], p2[0])
                x0 = p1e[pos1[n * SL + l] * PDIM + 4];
                x1 = p2e[pos2[n * SL + l] * PDIM + 0];
            } else {                                     // p2 pairs
                int tok = pos2[n * SL + l];
                x0 = p2e[tok * PDIM + (e0 - 55)];
                x1 = p2e[tok * PDIM + (e0 - 54)];
            }
            __half h0 = __float2half_rn(x0);
            __half h1 = __float2half_rn(x1);
            uint32_t uh = (uint32_t)__half_as_ushort(h0)
                        | ((uint32_t)__half_as_ushort(h1) << 16);
            uint32_t p   = (uint32_t)(l + 1);
            uint32_t off = p * 128u + (((uint32_t)e0 * 2u) ^ ((p & 7u) << 4));
            sts32(base + OFF_AH + off, uh);
        }
        __syncthreads();

        // ================= MMA phase (single term) =================
        float acc[4][8][4];
        #pragma unroll
        for (int mb = 0; mb < 4; mb++)
            #pragma unroll
            for (int nt = 0; nt < 8; nt++)
                #pragma unroll
                for (int q = 0; q < 4; q++) acc[mb][nt][q] = 0.f;

        for (int t = 0; t < 3; t++) {
            #pragma unroll
            for (int ks = 0; ks < 4; ks++) {
                uint32_t bh[4][4];
                const uint32_t kbB = (uint32_t)(t * 128 + ks * 32) + bkb;
                #pragma unroll
                for (int pp = 0; pp < 4; pp++) {
                    if (pp < npair) {
                        uint32_t c = (uint32_t)(nt0 + 2 * pp) * 8u + brow;
                        uint32_t off = c * 384u + (kbB ^ ((c & 7u) << 4));
                        ldsm4(bh[pp][0], bh[pp][1], bh[pp][2], bh[pp][3],
                              base + OFF_B + off);
                    }
                }
                const uint32_t kbA = (uint32_t)(ks * 32) + lkb;
                #pragma unroll
                for (int mb = 0; mb < 4; mb++) {
                    uint32_t r = (uint32_t)(msplit * 64 + mb * 16 + t) + lrow;
                    uint32_t aoff = r * 128u + (kbA ^ ((r & 7u) << 4));
                    uint32_t ah[4];
                    ldsm4(ah[0], ah[1], ah[2], ah[3], base + OFF_AH + aoff);
                    #pragma unroll
                    for (int nt = 0; nt < 8; nt++) {
                        if (nt < ntn) {
                            int pp = nt >> 1, hf = (nt & 1) * 2;
                            mma16816(acc[mb][nt], ah, bh[pp][hf], bh[pp][hf + 1]);
                        }
                    }
                }
            }
        }

        // ================= epilogue: max over positions =================
        #pragma unroll
        for (int nt = 0; nt < 8; nt++) {
            if (nt < ntn) {
                float ve = -1e30f, vo = -1e30f;
                #pragma unroll
                for (int mb = 0; mb < 4; mb++) {
                    ve = fmaxf(ve, fmaxf(acc[mb][nt][0], acc[mb][nt][2]));
                    vo = fmaxf(vo, fmaxf(acc[mb][nt][1], acc[mb][nt][3]));
                }
                #pragma unroll
                for (int o = 4; o <= 16; o <<= 1) {
                    ve = fmaxf(ve, __shfl_xor_sync(0xffffffffu, ve, o));
                    vo = fmaxf(vo, __shfl_xor_sync(0xffffffffu, vo, o));
                }
                if (lane < 4) {
                    int col = (nt0 + nt) * 8 + 2 * lane;
                    scr[msplit * NPC2 + col]     = ve;
                    scr[msplit * NPC2 + col + 1] = vo;
                }
            }
        }
        __syncthreads();
        if (tid < HID) {
            float m  = fmaxf(scr[tid], scr[NPC2 + tid]);
            float hv = m + conv_b[tid];
            g_h[n * HID + tid] = hv > 0.f ? hv : 0.f;
        }
        __syncthreads();
    }
}

// ---------------- kernel 2: bag attention + classifier ----------------
__global__ void __launch_bounds__(256) bag_kernel(
    const int* __restrict__ scope, const int* __restrict__ relation,
    const float* __restrict__ rel_w, const float* __restrict__ rel_b,
    float* __restrict__ out)
{
    __shared__ float rq[HID];
    __shared__ float rep[HID];
    __shared__ float logits[64];
    __shared__ float alpha[64];

    const int b = blockIdx.x, tid = threadIdx.x;
    const int wid = tid >> 5, lane = tid & 31;
    const int s0 = scope[2 * b], s1 = scope[2 * b + 1];
    const int sz = s1 - s0;
    const int rel = relation[b];

    for (int d = tid; d < HID; d += 256) rq[d] = rel_w[rel * HID + d];
    __syncthreads();

    for (int i = wid; i < sz && i < 64; i += 8) {
        const float* hr = g_h + (s0 + i) * HID;
        float s = 0.f;
        for (int d = lane; d < HID; d += 32) s += hr[d] * rq[d];
        #pragma unroll
        for (int o = 16; o > 0; o >>= 1) s += __shfl_xor_sync(0xffffffffu, s, o);
        if (lane == 0) logits[i] = s;
    }
    __syncthreads();

    if (tid == 0) {
        float m = -1e30f;
        for (int i = 0; i < sz && i < 64; i++) m = fmaxf(m, logits[i]);
        float den = 0.f;
        for (int i = 0; i < sz && i < 64; i++) {
            float e = expf(logits[i] - m);
            alpha[i] = e; den += e;
        }
        float inv = 1.f / den;
        for (int i = 0; i < sz && i < 64; i++) alpha[i] *= inv;
    }
    __syncthreads();

    for (int d = tid; d < HID; d += 256) {
        float a = 0.f;
        for (int i = 0; i < sz && i < 64; i++)
            a += alpha[i] * g_h[(s0 + i) * HID + d];
        rep[d] = a;
    }
    __syncthreads();

    for (int r = wid; r < NREL; r += 8) {
        float s = 0.f;
        for (int d = lane; d < HID; d += 32) s += rep[d] * rel_w[r * HID + d];
        #pragma unroll
        for (int o = 16; o > 0; o >>= 1) s += __shfl_xor_sync(0xffffffffu, s, o);
        if (lane == 0) out[b * NREL + r] = s + rel_b[r];
    }
}

// ---------------------------------------------------------------------------
extern "C" void kernel_launch(void* const* d_in, const int* in_sizes, int n_in,
                              void* d_out, int out_size)
{
    const int*   X        = (const int*)d_in[0];
    const int*   pos1     = (const int*)d_in[1];
    const int*   pos2     = (const int*)d_in[2];
    const int*   scope    = (const int*)d_in[5];
    const int*   relation = (const int*)d_in[6];
    const float* word_emb = (const float*)d_in[7];
    const float* p1e      = (const float*)d_in[8];
    const float* p2e      = (const float*)d_in[9];
    const float* conv_w   = (const float*)d_in[10];
    const float* conv_b   = (const float*)d_in[11];
    const float* rel_w    = (const float*)d_in[12];
    const float* rel_b    = (const float*)d_in[13];
    float*       out      = (float*)d_out;

    cudaFuncSetAttribute(enc_kernel,
                         cudaFuncAttributeMaxDynamicSharedMemorySize, SMEM_NEED);

    prepB<<<(NPC2 * KT + 255) / 256, 256>>>(conv_w);
    enc_kernel<<<GRID_ENC, 256, SMEM_NEED>>>(X, pos1, pos2, word_emb, p1e, p2e,
                                             conv_b);
    bag_kernel<<<NBAG, 256>>>(scope, relation, rel_w, rel_b, out);
}

// round 12
// speedup vs baseline: 1.7766x; 1.1213x over previous
#include <cuda_runtime.h>
#include <cuda_fp16.h>
#include <math.h>
#include <stdint.h>

// ---------------- problem constants ----------------
#define NS   4000
#define SL   128
#define VEC  50
#define PDIM 5
#define EMB  60
#define HID  230
#define NBAG 500
#define NREL 25

#define NPC2 240          // channels padded to 30 n-tiles (ldsm4 pairs)
#define KT   192          // K = 3 taps * 64
#define GRID_ENC 152      // 1 CTA per SM

// smem offsets (base 128-aligned)
#define OFF_B    0u             // 240*384 = 92160
#define OFF_A0   92160u         // 130 rows * 128B = 16640
#define OFF_A1   108800u        // second A buffer
#define OFF_SCR  125440u        // 2*240*4 = 1920
#define SMEM_NEED (127360 + 128)

__device__ float g_h[NS * HID];
__device__ __half g_B[NPC2 * KT];

// ---------------- helpers ----------------
__device__ __forceinline__ uint32_t smem_u32(const void* p) {
    uint32_t a;
    asm("{ .reg .u64 t; cvta.to.shared.u64 t, %1; cvt.u32.u64 %0, t; }"
        : "=r"(a) : "l"(p));
    return a;
}
__device__ __forceinline__ void sts32(uint32_t a, uint32_t v) {
    asm volatile("st.shared.u32 [%0], %1;" :: "r"(a), "r"(v));
}
__device__ __forceinline__ void sts64(uint32_t a, uint2 v) {
    asm volatile("st.shared.v2.u32 [%0], {%1,%2};" :: "r"(a), "r"(v.x), "r"(v.y));
}
__device__ __forceinline__ void sts128z(uint32_t a) {
    asm volatile("st.shared.v4.u32 [%0], {%1,%1,%1,%1};" :: "r"(a), "r"(0u));
}
__device__ __forceinline__ void ldsm4(uint32_t& r0, uint32_t& r1, uint32_t& r2,
                                      uint32_t& r3, uint32_t addr) {
    asm volatile("ldmatrix.sync.aligned.m8n8.x4.shared.b16 {%0,%1,%2,%3}, [%4];"
                 : "=r"(r0), "=r"(r1), "=r"(r2), "=r"(r3) : "r"(addr));
}
__device__ __forceinline__ void mma16816(float* c, const uint32_t* a,
                                         uint32_t b0, uint32_t b1) {
    asm volatile(
        "mma.sync.aligned.m16n8k16.row.col.f32.f16.f16.f32 "
        "{%0,%1,%2,%3}, {%4,%5,%6,%7}, {%8,%9}, {%0,%1,%2,%3};"
        : "+f"(c[0]), "+f"(c[1]), "+f"(c[2]), "+f"(c[3])
        : "r"(a[0]), "r"(a[1]), "r"(a[2]), "r"(a[3]), "r"(b0), "r"(b1));
}

// gather one (l, e0-pair) element pair of sentence n
__device__ __forceinline__ float2 gather_pair(
    int n, int idx,
    const int* __restrict__ X, const int* __restrict__ pos1,
    const int* __restrict__ pos2,
    const float* __restrict__ word_emb, const float* __restrict__ p1e,
    const float* __restrict__ p2e)
{
    int l = idx / 30, ep = idx - l * 30;
    int e0 = ep * 2;
    float x0, x1;
    if (e0 <= VEC - 2) {                         // word pairs
        int tok = X[n * SL + l];
        float2 w = *reinterpret_cast<const float2*>(word_emb + tok * VEC + e0);
        x0 = w.x; x1 = w.y;
    } else if (e0 < 54) {                        // p1 pairs
        int tok = pos1[n * SL + l];
        x0 = p1e[tok * PDIM + (e0 - 50)];
        x1 = p1e[tok * PDIM + (e0 - 49)];
    } else if (e0 == 54) {                       // boundary (p1[4], p2[0])
        x0 = p1e[pos1[n * SL + l] * PDIM + 4];
        x1 = p2e[pos2[n * SL + l] * PDIM + 0];
    } else {                                     // p2 pairs
        int tok = pos2[n * SL + l];
        x0 = p2e[tok * PDIM + (e0 - 55)];
        x1 = p2e[tok * PDIM + (e0 - 54)];
    }
    return make_float2(x0, x1);
}

// ---------------- kernel 0: conv_w -> fp16 im2col [c][tap*64+e] -------------
__global__ void prepB(const float* __restrict__ conv_w) {
    int idx = blockIdx.x * blockDim.x + threadIdx.x;
    if (idx >= NPC2 * KT) return;
    int c = idx / KT, k = idx - c * KT;
    int tap = k >> 6, e = k & 63;
    float v = 0.f;
    if (c < HID && e < EMB) v = conv_w[(c * EMB + e) * 3 + tap];
    g_B[idx] = __float2half_rn(v);
}

// ---------------- kernel 1: persistent mma.sync encoder ---------------------
// Single-term fp16 with SOFTWARE-PIPELINED A build: gathers for sentence
// n+GRID issue into registers before the MMA phase (latency hidden under
// ~8us of tensor work), converted+stored to the inactive A buffer after.
__global__ void __launch_bounds__(256, 1) enc_kernel(
    const int* __restrict__ X, const int* __restrict__ pos1,
    const int* __restrict__ pos2,
    const float* __restrict__ word_emb, const float* __restrict__ p1e,
    const float* __restrict__ p2e, const float* __restrict__ conv_b)
{
    extern __shared__ char sm_raw[];
    const uint32_t raw  = smem_u32(sm_raw);
    const uint32_t base = (raw + 127u) & ~127u;
    float* scr = (float*)(sm_raw + (base - raw) + OFF_SCR);

    const int tid  = threadIdx.x;
    const int wid  = tid >> 5;
    const int lane = tid & 31;

    // ---- stage resident B, swizzled rows of 384B
    for (int t = tid; t < NPC2 * KT / 4; t += 256) {
        int idx = t * 4;
        int c = idx / KT, k = idx - c * KT;
        uint32_t off = (uint32_t)c * 384u
                     + (((uint32_t)k * 2u) ^ (((uint32_t)(c & 7)) << 4));
        sts64(base + OFF_B + off, *reinterpret_cast<const uint2*>(g_B + idx));
    }
    // ---- zero BOTH A slabs once (pads persist)
    for (int t = tid; t < 2 * 16640 / 16; t += 256)
        sts128z(base + OFF_A0 + (uint32_t)t * 16u);
    __syncthreads();

    // ---- per-warp tiling
    const int msplit = wid >> 2;
    const int nsplit = wid & 3;
    const int nt0    = nsplit * 8;
    const int ntn    = (nsplit < 3) ? 8 : 6;
    const int npair  = ntn >> 1;

    // ldmatrix lane addressing
    const uint32_t lrow = (uint32_t)((lane & 7) + ((lane >> 3) & 1) * 8);
    const uint32_t lkb  = ((uint32_t)(lane >> 4) & 1u) * 16u;
    const uint32_t brow = (uint32_t)((lane & 7) + ((lane >> 4) & 1) * 8);
    const uint32_t bkb  = ((uint32_t)(lane >> 3) & 1u) * 16u;

    // ---- preamble: build sentence blockIdx.x into slab 0
    {
        float2 pre[15];
        #pragma unroll
        for (int it = 0; it < 15; it++)
            pre[it] = gather_pair(blockIdx.x, tid + it * 256,
                                  X, pos1, pos2, word_emb, p1e, p2e);
        #pragma unroll
        for (int it = 0; it < 15; it++) {
            int idx = tid + it * 256;
            int l = idx / 30, ep = idx - l * 30;
            int e0 = ep * 2;
            __half h0 = __float2half_rn(pre[it].x);
            __half h1 = __float2half_rn(pre[it].y);
            uint32_t uh = (uint32_t)__half_as_ushort(h0)
                        | ((uint32_t)__half_as_ushort(h1) << 16);
            uint32_t p   = (uint32_t)(l + 1);
            uint32_t off = p * 128u + (((uint32_t)e0 * 2u) ^ ((p & 7u) << 4));
            sts32(base + OFF_A0 + off, uh);
        }
    }
    __syncthreads();

    uint32_t abuf = OFF_A0;
    for (int n = blockIdx.x; n < NS; n += GRID_ENC) {
        const int nnext = n + GRID_ENC;
        const uint32_t anext = (abuf == OFF_A0) ? OFF_A1 : OFF_A0;

        // ---- stage 1: issue gathers for next sentence (latency hidden)
        float2 pre[15];
        if (nnext < NS) {
            #pragma unroll
            for (int it = 0; it < 15; it++)
                pre[it] = gather_pair(nnext, tid + it * 256,
                                      X, pos1, pos2, word_emb, p1e, p2e);
        }

        // ---- stage 2: MMA on current slab
        float acc[4][8][4];
        #pragma unroll
        for (int mb = 0; mb < 4; mb++)
            #pragma unroll
            for (int nt = 0; nt < 8; nt++)
                #pragma unroll
                for (int q = 0; q < 4; q++) acc[mb][nt][q] = 0.f;

        for (int t = 0; t < 3; t++) {
            #pragma unroll
            for (int ks = 0; ks < 4; ks++) {
                uint32_t bh[4][4];
                const uint32_t kbB = (uint32_t)(t * 128 + ks * 32) + bkb;
                #pragma unroll
                for (int pp = 0; pp < 4; pp++) {
                    if (pp < npair) {
                        uint32_t c = (uint32_t)(nt0 + 2 * pp) * 8u + brow;
                        uint32_t off = c * 384u + (kbB ^ ((c & 7u) << 4));
                        ldsm4(bh[pp][0], bh[pp][1], bh[pp][2], bh[pp][3],
                              base + OFF_B + off);
                    }
                }
                const uint32_t kbA = (uint32_t)(ks * 32) + lkb;
                #pragma unroll
                for (int mb = 0; mb < 4; mb++) {
                    uint32_t r = (uint32_t)(msplit * 64 + mb * 16 + t) + lrow;
                    uint32_t aoff = r * 128u + (kbA ^ ((r & 7u) << 4));
                    uint32_t ah[4];
                    ldsm4(ah[0], ah[1], ah[2], ah[3], base + abuf + aoff);
                    #pragma unroll
                    for (int nt = 0; nt < 8; nt++) {
                        if (nt < ntn) {
                            int pp = nt >> 1, hf = (nt & 1) * 2;
                            mma16816(acc[mb][nt], ah, bh[pp][hf], bh[pp][hf + 1]);
                        }
                    }
                }
            }
        }

        // ---- stage 3: convert + store prefetched data to inactive slab
        if (nnext < NS) {
            #pragma unroll
            for (int it = 0; it < 15; it++) {
                int idx = tid + it * 256;
                int l = idx / 30, ep = idx - l * 30;
                int e0 = ep * 2;
                __half h0 = __float2half_rn(pre[it].x);
                __half h1 = __float2half_rn(pre[it].y);
                uint32_t uh = (uint32_t)__half_as_ushort(h0)
                            | ((uint32_t)__half_as_ushort(h1) << 16);
                uint32_t p   = (uint32_t)(l + 1);
                uint32_t off = p * 128u + (((uint32_t)e0 * 2u) ^ ((p & 7u) << 4));
                sts32(base + anext + off, uh);
            }
        }

        // ---- epilogue: max over positions (scr written before sync)
        #pragma unroll
        for (int nt = 0; nt < 8; nt++) {
            if (nt < ntn) {
                float ve = -1e30f, vo = -1e30f;
                #pragma unroll
                for (int mb = 0; mb < 4; mb++) {
                    ve = fmaxf(ve, fmaxf(acc[mb][nt][0], acc[mb][nt][2]));
                    vo = fmaxf(vo, fmaxf(acc[mb][nt][1], acc[mb][nt][3]));
                }
                #pragma unroll
                for (int o = 4; o <= 16; o <<= 1) {
                    ve = fmaxf(ve, __shfl_xor_sync(0xffffffffu, ve, o));
                    vo = fmaxf(vo, __shfl_xor_sync(0xffffffffu, vo, o));
                }
                if (lane < 4) {
                    int col = (nt0 + nt) * 8 + 2 * lane;
                    scr[msplit * NPC2 + col]     = ve;
                    scr[msplit * NPC2 + col + 1] = vo;
                }
            }
        }
        __syncthreads();           // A-stores + scr visible
        if (tid < HID) {
            float m  = fmaxf(scr[tid], scr[NPC2 + tid]);
            float hv = m + conv_b[tid];
            g_h[n * HID + tid] = hv > 0.f ? hv : 0.f;
        }
        __syncthreads();           // scr safe to rewrite next iteration
        abuf = anext;
    }
}

// ---------------- kernel 2: bag attention + classifier ----------------
__global__ void __launch_bounds__(256) bag_kernel(
    const int* __restrict__ scope, const int* __restrict__ relation,
    const float* __restrict__ rel_w, const float* __restrict__ rel_b,
    float* __restrict__ out)
{
    __shared__ float rq[HID];
    __shared__ float rep[HID];
    __shared__ float logits[64];
    __shared__ float alpha[64];

    const int b = blockIdx.x, tid = threadIdx.x;
    const int wid = tid >> 5, lane = tid & 31;
    const int s0 = scope[2 * b], s1 = scope[2 * b + 1];
    const int sz = s1 - s0;
    const int rel = relation[b];

    for (int d = tid; d < HID; d += 256) rq[d] = rel_w[rel * HID + d];
    __syncthreads();

    for (int i = wid; i < sz && i < 64; i += 8) {
        const float* hr = g_h + (s0 + i) * HID;
        float s = 0.f;
        for (int d = lane; d < HID; d += 32) s += hr[d] * rq[d];
        #pragma unroll
        for (int o = 16; o > 0; o >>= 1) s += __shfl_xor_sync(0xffffffffu, s, o);
        if (lane == 0) logits[i] = s;
    }
    __syncthreads();

    if (tid == 0) {
        float m = -1e30f;
        for (int i = 0; i < sz && i < 64; i++) m = fmaxf(m, logits[i]);
        float den = 0.f;
        for (int i = 0; i < sz && i < 64; i++) {
            float e = expf(logits[i] - m);
            alpha[i] = e; den += e;
        }
        float inv = 1.f / den;
        for (int i = 0; i < sz && i < 64; i++) alpha[i] *= inv;
    }
    __syncthreads();

    for (int d = tid; d < HID; d += 256) {
        float a = 0.f;
        for (int i = 0; i < sz && i < 64; i++)
            a += alpha[i] * g_h[(s0 + i) * HID + d];
        rep[d] = a;
    }
    __syncthreads();

    for (int r = wid; r < NREL; r += 8) {
        float s = 0.f;
        for (int d = lane; d < HID; d += 32) s += rep[d] * rel_w[r * HID + d];
        #pragma unroll
        for (int o = 16; o > 0; o >>= 1) s += __shfl_xor_sync(0xffffffffu, s, o);
        if (lane == 0) out[b * NREL + r] = s + rel_b[r];
    }
}

// ---------------------------------------------------------------------------
extern "C" void kernel_launch(void* const* d_in, const int* in_sizes, int n_in,
                              void* d_out, int out_size)
{
    const int*   X        = (const int*)d_in[0];
    const int*   pos1     = (const int*)d_in[1];
    const int*   pos2     = (const int*)d_in[2];
    const int*   scope    = (const int*)d_in[5];
    const int*   relation = (const int*)d_in[6];
    const float* word_emb = (const float*)d_in[7];
    const float* p1e      = (const float*)d_in[8];
    const float* p2e      = (const float*)d_in[9];
    const float* conv_w   = (const float*)d_in[10];
    const float* conv_b   = (const float*)d_in[11];
    const float* rel_w    = (const float*)d_in[12];
    const float* rel_b    = (const float*)d_in[13];
    float*       out      = (float*)d_out;

    cudaFuncSetAttribute(enc_kernel,
                         cudaFuncAttributeMaxDynamicSharedMemorySize, SMEM_NEED);

    prepB<<<(NPC2 * KT + 255) / 256, 256>>>(conv_w);
    enc_kernel<<<GRID_ENC, 256, SMEM_NEED>>>(X, pos1, pos2, word_emb, p1e, p2e,
                                             conv_b);
    bag_kernel<<<NBAG, 256>>>(scope, relation, rel_w, rel_b, out);
}

// round 13
// speedup vs baseline: 2.1399x; 1.2045x over previous
#include <cuda_runtime.h>
#include <cuda_fp16.h>
#include <math.h>
#include <stdint.h>

// ---------------- problem constants ----------------
#define NS   4000
#define SL   128
#define VEC  50
#define PDIM 5
#define EMB  60
#define HID  230
#define NBAG 500
#define NREL 25

#define NPC2 240          // channels padded to 30 n-tiles
#define KT   192          // K = 3 taps * 64
#define GRID_ENC 152      // 1 CTA per SM
#define NQ   1920         // SL * 15 e-quads

// smem offsets (base 128-aligned)
#define OFF_B    0u             // 240*384 = 92160
#define OFF_A0   92160u         // 130 rows * 128B = 16640
#define OFF_A1   108800u        // second A buffer
#define SMEM_NEED (125440 + 128)

__device__ float g_h[NS * HID];
__device__ __half g_B[NPC2 * KT];

// ---------------- helpers ----------------
__device__ __forceinline__ uint32_t smem_u32(const void* p) {
    uint32_t a;
    asm("{ .reg .u64 t; cvta.to.shared.u64 t, %1; cvt.u32.u64 %0, t; }"
        : "=r"(a) : "l"(p));
    return a;
}
__device__ __forceinline__ void sts64(uint32_t a, uint2 v) {
    asm volatile("st.shared.v2.u32 [%0], {%1,%2};" :: "r"(a), "r"(v.x), "r"(v.y));
}
__device__ __forceinline__ void sts128z(uint32_t a) {
    asm volatile("st.shared.v4.u32 [%0], {%1,%1,%1,%1};" :: "r"(a), "r"(0u));
}
__device__ __forceinline__ void ldsm4(uint32_t& r0, uint32_t& r1, uint32_t& r2,
                                      uint32_t& r3, uint32_t addr) {
    asm volatile("ldmatrix.sync.aligned.m8n8.x4.shared.b16 {%0,%1,%2,%3}, [%4];"
                 : "=r"(r0), "=r"(r1), "=r"(r2), "=r"(r3) : "r"(addr));
}
__device__ __forceinline__ void mma16816(float* c, const uint32_t* a,
                                         uint32_t b0, uint32_t b1) {
    asm volatile(
        "mma.sync.aligned.m16n8k16.row.col.f32.f16.f16.f32 "
        "{%0,%1,%2,%3}, {%4,%5,%6,%7}, {%8,%9}, {%0,%1,%2,%3};"
        : "+f"(c[0]), "+f"(c[1]), "+f"(c[2]), "+f"(c[3])
        : "r"(a[0]), "r"(a[1]), "r"(a[2]), "r"(a[3]), "r"(b0), "r"(b1));
}

// gather one (l, e0..e0+3) quad of sentence n  (idx -> l = idx/15, q = idx%15)
__device__ __forceinline__ float4 gather_quad(
    int n, int idx,
    const int* __restrict__ X, const int* __restrict__ pos1,
    const int* __restrict__ pos2,
    const float* __restrict__ word_emb, const float* __restrict__ p1e,
    const float* __restrict__ p2e)
{
    int l = idx / 15, q = idx - l * 15;
    int e0 = q * 4;
    float x0, x1, x2, x3;
    if (e0 <= 44) {                              // pure word quad
        int tok = X[n * SL + l];
        float2 a = *reinterpret_cast<const float2*>(word_emb + tok * VEC + e0);
        float2 b = *reinterpret_cast<const float2*>(word_emb + tok * VEC + e0 + 2);
        x0 = a.x; x1 = a.y; x2 = b.x; x3 = b.y;
    } else if (e0 == 48) {                       // word[48,49], p1[0,1]
        int tok = X[n * SL + l];
        float2 a = *reinterpret_cast<const float2*>(word_emb + tok * VEC + 48);
        int t1 = pos1[n * SL + l];
        x0 = a.x; x1 = a.y;
        x2 = p1e[t1 * PDIM + 0]; x3 = p1e[t1 * PDIM + 1];
    } else if (e0 == 52) {                       // p1[2,3,4], p2[0]
        int t1 = pos1[n * SL + l];
        int t2 = pos2[n * SL + l];
        x0 = p1e[t1 * PDIM + 2]; x1 = p1e[t1 * PDIM + 3];
        x2 = p1e[t1 * PDIM + 4]; x3 = p2e[t2 * PDIM + 0];
    } else {                                     // e0 == 56: p2[1..4]
        int t2 = pos2[n * SL + l];
        x0 = p2e[t2 * PDIM + 1]; x1 = p2e[t2 * PDIM + 2];
        x2 = p2e[t2 * PDIM + 3]; x3 = p2e[t2 * PDIM + 4];
    }
    return make_float4(x0, x1, x2, x3);
}

__device__ __forceinline__ void store_quad(uint32_t slab, int idx, float4 v) {
    int l = idx / 15, q = idx - l * 15;
    uint32_t e0b = (uint32_t)(q * 8);            // byte offset of quad in row
    __half2 h01 = __float22half2_rn(make_float2(v.x, v.y));
    __half2 h23 = __float22half2_rn(make_float2(v.z, v.w));
    uint2 u;
    u.x = *reinterpret_cast<uint32_t*>(&h01);
    u.y = *reinterpret_cast<uint32_t*>(&h23);
    uint32_t p   = (uint32_t)(l + 1);
    uint32_t off = p * 128u + (e0b ^ ((p & 7u) << 4));
    sts64(slab + off, u);
}

// ---------------- kernel 0: conv_w -> fp16 im2col [c][tap*64+e] -------------
__global__ void prepB(const float* __restrict__ conv_w) {
    int idx = blockIdx.x * blockDim.x + threadIdx.x;
    if (idx >= NPC2 * KT) return;
    int c = idx / KT, k = idx - c * KT;
    int tap = k >> 6, e = k & 63;
    float v = 0.f;
    if (c < HID && e < EMB) v = conv_w[(c * EMB + e) * 3 + tap];
    g_B[idx] = __float2half_rn(v);
}

// ---------------- kernel 1: persistent mma.sync encoder ---------------------
// Single-term fp16, pipelined A build, N-ONLY warp split: warp w owns n-tiles
// [4w, 4w+4) (warp 7: 2 tiles) across ALL 128 m-rows -> epilogue is warp-local
// (no smem scratch, ONE sync per sentence).
__global__ void __launch_bounds__(256, 1) enc_kernel(
    const int* __restrict__ X, const int* __restrict__ pos1,
    const int* __restrict__ pos2,
    const float* __restrict__ word_emb, const float* __restrict__ p1e,
    const float* __restrict__ p2e, const float* __restrict__ conv_b)
{
    extern __shared__ char sm_raw[];
    const uint32_t raw  = smem_u32(sm_raw);
    const uint32_t base = (raw + 127u) & ~127u;

    const int tid  = threadIdx.x;
    const int wid  = tid >> 5;
    const int lane = tid & 31;

    // ---- stage resident B, swizzled rows of 384B
    for (int t = tid; t < NPC2 * KT / 4; t += 256) {
        int idx = t * 4;
        int c = idx / KT, k = idx - c * KT;
        uint32_t off = (uint32_t)c * 384u
                     + (((uint32_t)k * 2u) ^ (((uint32_t)(c & 7)) << 4));
        sts64(base + OFF_B + off, *reinterpret_cast<const uint2*>(g_B + idx));
    }
    // ---- zero BOTH A slabs once (pads persist)
    for (int t = tid; t < 2 * 16640 / 16; t += 256)
        sts128z(base + OFF_A0 + (uint32_t)t * 16u);
    __syncthreads();

    // ---- per-warp tiling: n-only split
    const int tilebase = wid * 4;
    const int ntiles   = (wid < 7) ? 4 : 2;
    const int npair    = ntiles >> 1;

    // ldmatrix lane addressing
    const uint32_t lrow = (uint32_t)((lane & 7) + ((lane >> 3) & 1) * 8);
    const uint32_t lkb  = ((uint32_t)(lane >> 4) & 1u) * 16u;
    const uint32_t brow = (uint32_t)((lane & 7) + ((lane >> 4) & 1) * 8);
    const uint32_t bkb  = ((uint32_t)(lane >> 3) & 1u) * 16u;

    // ---- preload bias for this lane's channels
    float cb0[4], cb1[4];
    #pragma unroll
    for (int nt = 0; nt < 4; nt++) {
        int col = (tilebase + nt) * 8 + 2 * (lane & 3);
        cb0[nt] = (nt < ntiles && col     < HID) ? conv_b[col]     : 0.f;
        cb1[nt] = (nt < ntiles && col + 1 < HID) ? conv_b[col + 1] : 0.f;
    }

    // ---- preamble: build sentence blockIdx.x into slab 0
    {
        float4 pre[8];
        #pragma unroll
        for (int it = 0; it < 8; it++) {
            int idx = tid + it * 256;
            if (idx < NQ)
                pre[it] = gather_quad(blockIdx.x, idx,
                                      X, pos1, pos2, word_emb, p1e, p2e);
        }
        #pragma unroll
        for (int it = 0; it < 8; it++) {
            int idx = tid + it * 256;
            if (idx < NQ) store_quad(base + OFF_A0, idx, pre[it]);
        }
    }
    __syncthreads();

    uint32_t abuf = OFF_A0;
    for (int n = blockIdx.x; n < NS; n += GRID_ENC) {
        const int nnext = n + GRID_ENC;
        const uint32_t anext = (abuf == OFF_A0) ? OFF_A1 : OFF_A0;

        // ---- stage 1: issue gathers for next sentence (latency hidden)
        float4 pre[8];
        if (nnext < NS) {
            #pragma unroll
            for (int it = 0; it < 8; it++) {
                int idx = tid + it * 256;
                if (idx < NQ)
                    pre[it] = gather_quad(nnext, idx,
                                          X, pos1, pos2, word_emb, p1e, p2e);
            }
        }

        // ---- stage 2: MMA on current slab
        float acc[8][4][4];
        #pragma unroll
        for (int mb = 0; mb < 8; mb++)
            #pragma unroll
            for (int nt = 0; nt < 4; nt++)
                #pragma unroll
                for (int q = 0; q < 4; q++) acc[mb][nt][q] = 0.f;

        for (int t = 0; t < 3; t++) {
            #pragma unroll
            for (int ks = 0; ks < 4; ks++) {
                uint32_t bh[2][4];
                const uint32_t kbB = (uint32_t)(t * 128 + ks * 32) + bkb;
                #pragma unroll
                for (int pp = 0; pp < 2; pp++) {
                    if (pp < npair) {
                        uint32_t c = (uint32_t)(tilebase + 2 * pp) * 8u + brow;
                        uint32_t off = c * 384u + (kbB ^ ((c & 7u) << 4));
                        ldsm4(bh[pp][0], bh[pp][1], bh[pp][2], bh[pp][3],
                              base + OFF_B + off);
                    }
                }
                const uint32_t kbA = (uint32_t)(ks * 32) + lkb;
                #pragma unroll
                for (int mb = 0; mb < 8; mb++) {
                    uint32_t r = (uint32_t)(mb * 16 + t) + lrow;
                    uint32_t aoff = r * 128u + (kbA ^ ((r & 7u) << 4));
                    uint32_t ah[4];
                    ldsm4(ah[0], ah[1], ah[2], ah[3], base + abuf + aoff);
                    #pragma unroll
                    for (int nt = 0; nt < 4; nt++) {
                        if (nt < ntiles) {
                            int pp = nt >> 1, hf = (nt & 1) * 2;
                            mma16816(acc[mb][nt], ah, bh[pp][hf], bh[pp][hf + 1]);
                        }
                    }
                }
            }
        }

        // ---- stage 3: convert + store prefetched data to inactive slab
        if (nnext < NS) {
            #pragma unroll
            for (int it = 0; it < 8; it++) {
                int idx = tid + it * 256;
                if (idx < NQ) store_quad(base + anext, idx, pre[it]);
            }
        }

        // ---- epilogue: warp-local max over all 128 positions, direct store
        #pragma unroll
        for (int nt = 0; nt < 4; nt++) {
            if (nt < ntiles) {
                float ve = -1e30f, vo = -1e30f;
                #pragma unroll
                for (int mb = 0; mb < 8; mb++) {
                    ve = fmaxf(ve, fmaxf(acc[mb][nt][0], acc[mb][nt][2]));
                    vo = fmaxf(vo, fmaxf(acc[mb][nt][1], acc[mb][nt][3]));
                }
                #pragma unroll
                for (int o = 4; o <= 16; o <<= 1) {
                    ve = fmaxf(ve, __shfl_xor_sync(0xffffffffu, ve, o));
                    vo = fmaxf(vo, __shfl_xor_sync(0xffffffffu, vo, o));
                }
                if (lane < 4) {
                    int col = (tilebase + nt) * 8 + 2 * lane;
                    if (col < HID) {
                        float hv = ve + cb0[nt];
                        g_h[n * HID + col] = hv > 0.f ? hv : 0.f;
                    }
                    if (col + 1 < HID) {
                        float hv = vo + cb1[nt];
                        g_h[n * HID + col + 1] = hv > 0.f ? hv : 0.f;
                    }
                }
            }
        }

        __syncthreads();     // A-stores to anext visible before next MMA phase
        abuf = anext;
    }
}

// ---------------- kernel 2: bag attention + classifier ----------------
__global__ void __launch_bounds__(256) bag_kernel(
    const int* __restrict__ scope, const int* __restrict__ relation,
    const float* __restrict__ rel_w, const float* __restrict__ rel_b,
    float* __restrict__ out)
{
    __shared__ float rq[HID];
    __shared__ float rep[HID];
    __shared__ float logits[64];
    __shared__ float alpha[64];

    const int b = blockIdx.x, tid = threadIdx.x;
    const int wid = tid >> 5, lane = tid & 31;
    const int s0 = scope[2 * b], s1 = scope[2 * b + 1];
    const int sz = s1 - s0;
    const int rel = relation[b];

    for (int d = tid; d < HID; d += 256) rq[d] = rel_w[rel * HID + d];
    __syncthreads();

    for (int i = wid; i < sz && i < 64; i += 8) {
        const float* hr = g_h + (s0 + i) * HID;
        float s = 0.f;
        for (int d = lane; d < HID; d += 32) s += hr[d] * rq[d];
        #pragma unroll
        for (int o = 16; o > 0; o >>= 1) s += __shfl_xor_sync(0xffffffffu, s, o);
        if (lane == 0) logits[i] = s;
    }
    __syncthreads();

    if (tid == 0) {
        float m = -1e30f;
        for (int i = 0; i < sz && i < 64; i++) m = fmaxf(m, logits[i]);
        float den = 0.f;
        for (int i = 0; i < sz && i < 64; i++) {
            float e = expf(logits[i] - m);
            alpha[i] = e; den += e;
        }
        float inv = 1.f / den;
        for (int i = 0; i < sz && i < 64; i++) alpha[i] *= inv;
    }
    __syncthreads();

    for (int d = tid; d < HID; d += 256) {
        float a = 0.f;
        for (int i = 0; i < sz && i < 64; i++)
            a += alpha[i] * g_h[(s0 + i) * HID + d];
        rep[d] = a;
    }
    __syncthreads();

    for (int r = wid; r < NREL; r += 8) {
        float s = 0.f;
        for (int d = lane; d < HID; d += 32) s += rep[d] * rel_w[r * HID + d];
        #pragma unroll
        for (int o = 16; o > 0; o >>= 1) s += __shfl_xor_sync(0xffffffffu, s, o);
        if (lane == 0) out[b * NREL + r] = s + rel_b[r];
    }
}

// ---------------------------------------------------------------------------
extern "C" void kernel_launch(void* const* d_in, const int* in_sizes, int n_in,
                              void* d_out, int out_size)
{
    const int*   X        = (const int*)d_in[0];
    const int*   pos1     = (const int*)d_in[1];
    const int*   pos2     = (const int*)d_in[2];
    const int*   scope    = (const int*)d_in[5];
    const int*   relation = (const int*)d_in[6];
    const float* word_emb = (const float*)d_in[7];
    const float* p1e      = (const float*)d_in[8];
    const float* p2e      = (const float*)d_in[9];
    const float* conv_w   = (const float*)d_in[10];
    const float* conv_b   = (const float*)d_in[11];
    const float* rel_w    = (const float*)d_in[12];
    const float* rel_b    = (const float*)d_in[13];
    float*       out      = (float*)d_out;

    cudaFuncSetAttribute(enc_kernel,
                         cudaFuncAttributeMaxDynamicSharedMemorySize, SMEM_NEED);

    prepB<<<(NPC2 * KT + 255) / 256, 256>>>(conv_w);
    enc_kernel<<<GRID_ENC, 256, SMEM_NEED>>>(X, pos1, pos2, word_emb, p1e, p2e,
                                             conv_b);
    bag_kernel<<<NBAG, 256>>>(scope, relation, rel_w, rel_b, out);
}

// round 14
// speedup vs baseline: 2.7619x; 1.2907x over previous
#include <cuda_runtime.h>
#include <cuda_fp16.h>
#include <math.h>
#include <stdint.h>

// ---------------- problem constants ----------------
#define NS   4000
#define SL   128
#define VEC  50
#define PDIM 5
#define EMB  60
#define HID  230
#define NBAG 500
#define NREL 25

#define NPC2 240          // channels padded to 30 n-tiles
#define KT   192          // K = 3 taps * 64
#define GRID_ENC 152      // 1 CTA per SM
#define NQ   1920         // SL * 15 e-quads
#define NTH  512

// smem offsets (base 128-aligned)
#define OFF_B    0u             // 240*384 = 92160
#define OFF_A0   92160u         // 130 rows * 128B = 16640
#define OFF_A1   108800u        // second A buffer
#define OFF_SCR  125440u        // 2 bufs * 2*240 floats = 3840
#define SMEM_NEED (129280 + 128)

__device__ float g_h[NS * HID];
__device__ __half g_B[NPC2 * KT];

// ---------------- helpers ----------------
__device__ __forceinline__ uint32_t smem_u32(const void* p) {
    uint32_t a;
    asm("{ .reg .u64 t; cvta.to.shared.u64 t, %1; cvt.u32.u64 %0, t; }"
        : "=r"(a) : "l"(p));
    return a;
}
__device__ __forceinline__ void sts64(uint32_t a, uint2 v) {
    asm volatile("st.shared.v2.u32 [%0], {%1,%2};" :: "r"(a), "r"(v.x), "r"(v.y));
}
__device__ __forceinline__ void sts128z(uint32_t a) {
    asm volatile("st.shared.v4.u32 [%0], {%1,%1,%1,%1};" :: "r"(a), "r"(0u));
}
__device__ __forceinline__ void ldsm4(uint32_t& r0, uint32_t& r1, uint32_t& r2,
                                      uint32_t& r3, uint32_t addr) {
    asm volatile("ldmatrix.sync.aligned.m8n8.x4.shared.b16 {%0,%1,%2,%3}, [%4];"
                 : "=r"(r0), "=r"(r1), "=r"(r2), "=r"(r3) : "r"(addr));
}
__device__ __forceinline__ void mma16816(float* c, const uint32_t* a,
                                         uint32_t b0, uint32_t b1) {
    asm volatile(
        "mma.sync.aligned.m16n8k16.row.col.f32.f16.f16.f32 "
        "{%0,%1,%2,%3}, {%4,%5,%6,%7}, {%8,%9}, {%0,%1,%2,%3};"
        : "+f"(c[0]), "+f"(c[1]), "+f"(c[2]), "+f"(c[3])
        : "r"(a[0]), "r"(a[1]), "r"(a[2]), "r"(a[3]), "r"(b0), "r"(b1));
}

// gather one (l, e0..e0+3) quad of sentence n, packed to half2x2
__device__ __forceinline__ uint2 gather_quad_packed(
    int n, int idx,
    const int* __restrict__ X, const int* __restrict__ pos1,
    const int* __restrict__ pos2,
    const float* __restrict__ word_emb, const float* __restrict__ p1e,
    const float* __restrict__ p2e)
{
    int l = idx / 15, q = idx - l * 15;
    int e0 = q * 4;
    float x0, x1, x2, x3;
    if (e0 <= 44) {                              // pure word quad
        int tok = X[n * SL + l];
        float2 a = *reinterpret_cast<const float2*>(word_emb + tok * VEC + e0);
        float2 b = *reinterpret_cast<const float2*>(word_emb + tok * VEC + e0 + 2);
        x0 = a.x; x1 = a.y; x2 = b.x; x3 = b.y;
    } else if (e0 == 48) {                       // word[48,49], p1[0,1]
        int tok = X[n * SL + l];
        float2 a = *reinterpret_cast<const float2*>(word_emb + tok * VEC + 48);
        int t1 = pos1[n * SL + l];
        x0 = a.x; x1 = a.y;
        x2 = p1e[t1 * PDIM + 0]; x3 = p1e[t1 * PDIM + 1];
    } else if (e0 == 52) {                       // p1[2,3,4], p2[0]
        int t1 = pos1[n * SL + l];
        int t2 = pos2[n * SL + l];
        x0 = p1e[t1 * PDIM + 2]; x1 = p1e[t1 * PDIM + 3];
        x2 = p1e[t1 * PDIM + 4]; x3 = p2e[t2 * PDIM + 0];
    } else {                                     // e0 == 56: p2[1..4]
        int t2 = pos2[n * SL + l];
        x0 = p2e[t2 * PDIM + 1]; x1 = p2e[t2 * PDIM + 2];
        x2 = p2e[t2 * PDIM + 3]; x3 = p2e[t2 * PDIM + 4];
    }
    __half2 h01 = __float22half2_rn(make_float2(x0, x1));
    __half2 h23 = __float22half2_rn(make_float2(x2, x3));
    uint2 u;
    u.x = *reinterpret_cast<uint32_t*>(&h01);
    u.y = *reinterpret_cast<uint32_t*>(&h23);
    return u;
}

__device__ __forceinline__ void store_quad(uint32_t slab, int idx, uint2 u) {
    int l = idx / 15, q = idx - l * 15;
    uint32_t e0b = (uint32_t)(q * 8);
    uint32_t p   = (uint32_t)(l + 1);
    uint32_t off = p * 128u + (e0b ^ ((p & 7u) << 4));
    sts64(slab + off, u);
}

// ---------------- kernel 0: conv_w -> fp16 im2col [c][tap*64+e] -------------
__global__ void prepB(const float* __restrict__ conv_w) {
    int idx = blockIdx.x * blockDim.x + threadIdx.x;
    if (idx >= NPC2 * KT) return;
    int c = idx / KT, k = idx - c * KT;
    int tap = k >> 6, e = k & 63;
    float v = 0.f;
    if (c < HID && e < EMB) v = conv_w[(c * EMB + e) * 3 + tap];
    g_B[idx] = __float2half_rn(v);
}

// ---------------- kernel 1: persistent mma.sync encoder ---------------------
// Single-term fp16; 512 threads (4 warps/SMSP); 2m x 8n warp split
// (msplit=wid>>3: 64 rows; nsplit=wid&7: 4 n-tiles, last warp-pair 2).
// Pipelined A build AND pipelined cross-warp epilogue (deferred finalize
// via double-buffered scr). One __syncthreads per sentence.
__global__ void __launch_bounds__(NTH, 1) enc_kernel(
    const int* __restrict__ X, const int* __restrict__ pos1,
    const int* __restrict__ pos2,
    const float* __restrict__ word_emb, const float* __restrict__ p1e,
    const float* __restrict__ p2e, const float* __restrict__ conv_b)
{
    extern __shared__ char sm_raw[];
    const uint32_t raw  = smem_u32(sm_raw);
    const uint32_t base = (raw + 127u) & ~127u;
    float* scr = (float*)(sm_raw + (base - raw) + OFF_SCR);  // [2][2*240]

    const int tid  = threadIdx.x;
    const int wid  = tid >> 5;
    const int lane = tid & 31;

    // ---- stage resident B, swizzled rows of 384B
    for (int t = tid; t < NPC2 * KT / 4; t += NTH) {
        int idx = t * 4;
        int c = idx / KT, k = idx - c * KT;
        uint32_t off = (uint32_t)c * 384u
                     + (((uint32_t)k * 2u) ^ (((uint32_t)(c & 7)) << 4));
        sts64(base + OFF_B + off, *reinterpret_cast<const uint2*>(g_B + idx));
    }
    // ---- zero BOTH A slabs once (pads persist)
    for (int t = tid; t < 2 * 16640 / 16; t += NTH)
        sts128z(base + OFF_A0 + (uint32_t)t * 16u);
    __syncthreads();

    // ---- per-warp tiling: 2m x 8n
    const int msplit = wid >> 3;            // rows [64*msplit, +64)
    const int nsplit = wid & 7;
    const int nt0    = nsplit * 4;
    const int ntiles = (nsplit < 7) ? 4 : 2;
    const int npair  = ntiles >> 1;

    // ldmatrix lane addressing
    const uint32_t lrow = (uint32_t)((lane & 7) + ((lane >> 3) & 1) * 8);
    const uint32_t lkb  = ((uint32_t)(lane >> 4) & 1u) * 16u;
    const uint32_t brow = (uint32_t)((lane & 7) + ((lane >> 4) & 1) * 8);
    const uint32_t bkb  = ((uint32_t)(lane >> 3) & 1u) * 16u;

    // ---- preamble: build sentence blockIdx.x into slab 0
    {
        uint2 pre[4];
        #pragma unroll
        for (int it = 0; it < 4; it++) {
            int idx = tid + it * NTH;
            if (idx < NQ)
                pre[it] = gather_quad_packed(blockIdx.x, idx,
                                             X, pos1, pos2, word_emb, p1e, p2e);
        }
        #pragma unroll
        for (int it = 0; it < 4; it++) {
            int idx = tid + it * NTH;
            if (idx < NQ) store_quad(base + OFF_A0, idx, pre[it]);
        }
    }
    __syncthreads();

    uint32_t abuf  = OFF_A0;
    int      sbuf  = 0;       // scr buffer this iteration writes
    int      nprev = -1;      // sentence whose partials await finalize
    for (int n = blockIdx.x; n < NS; n += GRID_ENC) {
        // ---- deferred finalize of previous sentence (overlaps this MMA)
        if (nprev >= 0 && tid < HID) {
            float* sp = scr + (sbuf ^ 1) * 2 * NPC2;
            float m  = fmaxf(sp[tid], sp[NPC2 + tid]);
            float hv = m + conv_b[tid];
            g_h[nprev * HID + tid] = hv > 0.f ? hv : 0.f;
        }

        const int nnext = n + GRID_ENC;
        const uint32_t anext = (abuf == OFF_A0) ? OFF_A1 : OFF_A0;

        // ---- stage 1: issue gathers for next sentence (latency hidden)
        uint2 pre[4];
        if (nnext < NS) {
            #pragma unroll
            for (int it = 0; it < 4; it++) {
                int idx = tid + it * NTH;
                if (idx < NQ)
                    pre[it] = gather_quad_packed(nnext, idx,
                                                 X, pos1, pos2, word_emb, p1e, p2e);
            }
        }

        // ---- stage 2: MMA on current slab
        float acc[4][4][4];
        #pragma unroll
        for (int mb = 0; mb < 4; mb++)
            #pragma unroll
            for (int nt = 0; nt < 4; nt++)
                #pragma unroll
                for (int q = 0; q < 4; q++) acc[mb][nt][q] = 0.f;

        for (int t = 0; t < 3; t++) {
            #pragma unroll
            for (int ks = 0; ks < 4; ks++) {
                uint32_t bh[2][4];
                const uint32_t kbB = (uint32_t)(t * 128 + ks * 32) + bkb;
                #pragma unroll
                for (int pp = 0; pp < 2; pp++) {
                    if (pp < npair) {
                        uint32_t c = (uint32_t)(nt0 + 2 * pp) * 8u + brow;
                        uint32_t off = c * 384u + (kbB ^ ((c & 7u) << 4));
                        ldsm4(bh[pp][0], bh[pp][1], bh[pp][2], bh[pp][3],
                              base + OFF_B + off);
                    }
                }
                const uint32_t kbA = (uint32_t)(ks * 32) + lkb;
                #pragma unroll
                for (int mb = 0; mb < 4; mb++) {
                    uint32_t r = (uint32_t)(msplit * 64 + mb * 16 + t) + lrow;
                    uint32_t aoff = r * 128u + (kbA ^ ((r & 7u) << 4));
                    uint32_t ah[4];
                    ldsm4(ah[0], ah[1], ah[2], ah[3], base + abuf + aoff);
                    #pragma unroll
                    for (int nt = 0; nt < 4; nt++) {
                        if (nt < ntiles) {
                            int pp = nt >> 1, hf = (nt & 1) * 2;
                            mma16816(acc[mb][nt], ah, bh[pp][hf], bh[pp][hf + 1]);
                        }
                    }
                }
            }
        }

        // ---- stage 3: convert + store prefetched data to inactive slab
        if (nnext < NS) {
            #pragma unroll
            for (int it = 0; it < 4; it++) {
                int idx = tid + it * NTH;
                if (idx < NQ) store_quad(base + anext, idx, pre[it]);
            }
        }

        // ---- epilogue: warp-local partial max -> scr[sbuf]
        #pragma unroll
        for (int nt = 0; nt < 4; nt++) {
            if (nt < ntiles) {
                float ve = -1e30f, vo = -1e30f;
                #pragma unroll
                for (int mb = 0; mb < 4; mb++) {
                    ve = fmaxf(ve, fmaxf(acc[mb][nt][0], acc[mb][nt][2]));
                    vo = fmaxf(vo, fmaxf(acc[mb][nt][1], acc[mb][nt][3]));
                }
                #pragma unroll
                for (int o = 4; o <= 16; o <<= 1) {
                    ve = fmaxf(ve, __shfl_xor_sync(0xffffffffu, ve, o));
                    vo = fmaxf(vo, __shfl_xor_sync(0xffffffffu, vo, o));
                }
                if (lane < 4) {
                    int col = (nt0 + nt) * 8 + 2 * lane;
                    float* sp = scr + sbuf * 2 * NPC2 + msplit * NPC2;
                    sp[col]     = ve;
                    sp[col + 1] = vo;
                }
            }
        }

        __syncthreads();   // A-stores + scr partials visible
        nprev = n;
        sbuf ^= 1;
        abuf  = anext;
    }

    // ---- tail finalize for the last sentence
    if (nprev >= 0 && tid < HID) {
        float* sp = scr + (sbuf ^ 1) * 2 * NPC2;
        float m  = fmaxf(sp[tid], sp[NPC2 + tid]);
        float hv = m + conv_b[tid];
        g_h[nprev * HID + tid] = hv > 0.f ? hv : 0.f;
    }
}

// ---------------- kernel 2: bag attention + classifier ----------------
__global__ void __launch_bounds__(256) bag_kernel(
    const int* __restrict__ scope, const int* __restrict__ relation,
    const float* __restrict__ rel_w, const float* __restrict__ rel_b,
    float* __restrict__ out)
{
    __shared__ float rq[HID];
    __shared__ float rep[HID];
    __shared__ float logits[64];
    __shared__ float alpha[64];

    const int b = blockIdx.x, tid = threadIdx.x;
    const int wid = tid >> 5, lane = tid & 31;
    const int s0 = scope[2 * b], s1 = scope[2 * b + 1];
    const int sz = s1 - s0;
    const int rel = relation[b];

    for (int d = tid; d < HID; d += 256) rq[d] = rel_w[rel * HID + d];
    __syncthreads();

    for (int i = wid; i < sz && i < 64; i += 8) {
        const float* hr = g_h + (s0 + i) * HID;
        float s = 0.f;
        for (int d = lane; d < HID; d += 32) s += hr[d] * rq[d];
        #pragma unroll
        for (int o = 16; o > 0; o >>= 1) s += __shfl_xor_sync(0xffffffffu, s, o);
        if (lane == 0) logits[i] = s;
    }
    __syncthreads();

    if (tid == 0) {
        float m = -1e30f;
        for (int i = 0; i < sz && i < 64; i++) m = fmaxf(m, logits[i]);
        float den = 0.f;
        for (int i = 0; i < sz && i < 64; i++) {
            float e = expf(logits[i] - m);
            alpha[i] = e; den += e;
        }
        float inv = 1.f / den;
        for (int i = 0; i < sz && i < 64; i++) alpha[i] *= inv;
    }
    __syncthreads();

    for (int d = tid; d < HID; d += 256) {
        float a = 0.f;
        for (int i = 0; i < sz && i < 64; i++)
            a += alpha[i] * g_h[(s0 + i) * HID + d];
        rep[d] = a;
    }
    __syncthreads();

    for (int r = wid; r < NREL; r += 8) {
        float s = 0.f;
        for (int d = lane; d < HID; d += 32) s += rep[d] * rel_w[r * HID + d];
        #pragma unroll
        for (int o = 16; o > 0; o >>= 1) s += __shfl_xor_sync(0xffffffffu, s, o);
        if (lane == 0) out[b * NREL + r] = s + rel_b[r];
    }
}

// ---------------------------------------------------------------------------
extern "C" void kernel_launch(void* const* d_in, const int* in_sizes, int n_in,
                              void* d_out, int out_size)
{
    const int*   X        = (const int*)d_in[0];
    const int*   pos1     = (const int*)d_in[1];
    const int*   pos2     = (const int*)d_in[2];
    const int*   scope    = (const int*)d_in[5];
    const int*   relation = (const int*)d_in[6];
    const float* word_emb = (const float*)d_in[7];
    const float* p1e      = (const float*)d_in[8];
    const float* p2e      = (const float*)d_in[9];
    const float* conv_w   = (const float*)d_in[10];
    const float* conv_b   = (const float*)d_in[11];
    const float* rel_w    = (const float*)d_in[12];
    const float* rel_b    = (const float*)d_in[13];
    float*       out      = (float*)d_out;

    cudaFuncSetAttribute(enc_kernel,
                         cudaFuncAttributeMaxDynamicSharedMemorySize, SMEM_NEED);

    prepB<<<(NPC2 * KT + 255) / 256, 256>>>(conv_w);
    enc_kernel<<<GRID_ENC, NTH, SMEM_NEED>>>(X, pos1, pos2, word_emb, p1e, p2e,
                                             conv_b);
    bag_kernel<<<NBAG, 256>>>(scope, relation, rel_w, rel_b, out);
}

// round 16
// speedup vs baseline: 2.7885x; 1.0096x over previous
#include <cuda_runtime.h>
#include <cuda_fp16.h>
#include <math.h>
#include <stdint.h>

// ---------------- problem constants ----------------
#define NS   4000
#define SL   128
#define VEC  50
#define PDIM 5
#define EMB  60
#define HID  230
#define NBAG 500
#define NREL 25

#define NPC2 240          // channels padded to 30 n-tiles
#define KT   192          // K = 3 taps * 64
#define GRID_ENC 152      // 1 CTA per SM
#define NQ   1920         // SL * 15 e-quads
#define NTH  512

// smem offsets (base 128-aligned)
#define OFF_B    0u             // 240*384 = 92160
#define OFF_A0   92160u         // 130 rows * 128B = 16640
#define OFF_A1   108800u        // second A buffer
#define OFF_SCR  125440u        // 2 bufs * 2*240 floats = 3840
#define SMEM_NEED (129280 + 128)

__device__ float g_h[NS * HID];

// ---------------- helpers ----------------
__device__ __forceinline__ uint32_t smem_u32(const void* p) {
    uint32_t a;
    asm("{ .reg .u64 t; cvta.to.shared.u64 t, %1; cvt.u32.u64 %0, t; }"
        : "=r"(a) : "l"(p));
    return a;
}
__device__ __forceinline__ void sts64(uint32_t a, uint2 v) {
    asm volatile("st.shared.v2.u32 [%0], {%1,%2};" :: "r"(a), "r"(v.x), "r"(v.y));
}
__device__ __forceinline__ void sts128z(uint32_t a) {
    asm volatile("st.shared.v4.u32 [%0], {%1,%1,%1,%1};" :: "r"(a), "r"(0u));
}
__device__ __forceinline__ void ldsm4(uint32_t& r0, uint32_t& r1, uint32_t& r2,
                                      uint32_t& r3, uint32_t addr) {
    asm volatile("ldmatrix.sync.aligned.m8n8.x4.shared.b16 {%0,%1,%2,%3}, [%4];"
                 : "=r"(r0), "=r"(r1), "=r"(r2), "=r"(r3) : "r"(addr));
}
__device__ __forceinline__ void mma16816(float* c, const uint32_t* a,
                                         uint32_t b0, uint32_t b1) {
    asm volatile(
        "mma.sync.aligned.m16n8k16.row.col.f32.f16.f16.f32 "
        "{%0,%1,%2,%3}, {%4,%5,%6,%7}, {%8,%9}, {%0,%1,%2,%3};"
        : "+f"(c[0]), "+f"(c[1]), "+f"(c[2]), "+f"(c[3])
        : "r"(a[0]), "r"(a[1]), "r"(a[2]), "r"(a[3]), "r"(b0), "r"(b1));
}

// gather one (l, e0..e0+3) quad of sentence n, packed to half2x2
__device__ __forceinline__ uint2 gather_quad_packed(
    int n, int idx,
    const int* __restrict__ X, const int* __restrict__ pos1,
    const int* __restrict__ pos2,
    const float* __restrict__ word_emb, const float* __restrict__ p1e,
    const float* __restrict__ p2e)
{
    int l = idx / 15, q = idx - l * 15;
    int e0 = q * 4;
    float x0, x1, x2, x3;
    if (e0 <= 44) {                              // pure word quad
        int tok = X[n * SL + l];
        float2 a = *reinterpret_cast<const float2*>(word_emb + tok * VEC + e0);
        float2 b = *reinterpret_cast<const float2*>(word_emb + tok * VEC + e0 + 2);
        x0 = a.x; x1 = a.y; x2 = b.x; x3 = b.y;
    } else if (e0 == 48) {                       // word[48,49], p1[0,1]
        int tok = X[n * SL + l];
        float2 a = *reinterpret_cast<const float2*>(word_emb + tok * VEC + 48);
        int t1 = pos1[n * SL + l];
        x0 = a.x; x1 = a.y;
        x2 = p1e[t1 * PDIM + 0]; x3 = p1e[t1 * PDIM + 1];
    } else if (e0 == 52) {                       // p1[2,3,4], p2[0]
        int t1 = pos1[n * SL + l];
        int t2 = pos2[n * SL + l];
        x0 = p1e[t1 * PDIM + 2]; x1 = p1e[t1 * PDIM + 3];
        x2 = p1e[t1 * PDIM + 4]; x3 = p2e[t2 * PDIM + 0];
    } else {                                     // e0 == 56: p2[1..4]
        int t2 = pos2[n * SL + l];
        x0 = p2e[t2 * PDIM + 1]; x1 = p2e[t2 * PDIM + 2];
        x2 = p2e[t2 * PDIM + 3]; x3 = p2e[t2 * PDIM + 4];
    }
    __half2 h01 = __float22half2_rn(make_float2(x0, x1));
    __half2 h23 = __float22half2_rn(make_float2(x2, x3));
    uint2 u;
    u.x = *reinterpret_cast<uint32_t*>(&h01);
    u.y = *reinterpret_cast<uint32_t*>(&h23);
    return u;
}

__device__ __forceinline__ void store_quad(uint32_t slab, int idx, uint2 u) {
    int l = idx / 15, q = idx - l * 15;
    uint32_t e0b = (uint32_t)(q * 8);
    uint32_t p   = (uint32_t)(l + 1);
    uint32_t off = p * 128u + (e0b ^ ((p & 7u) << 4));
    sts64(slab + off, u);
}

// ---------------- kernel 1: persistent mma.sync encoder ---------------------
// Single-term fp16; 512 threads; SMSP-BALANCED tiling: smsp=wid&3 ->
// ms=(smsp>=2), half=smsp&1, rank r=wid>>2; warp covers n-tiles
// [half*15 + 4r, +4) (r=3: +3) x rows [64*ms, +64). Every SMSP = 15
// tile-units = 720 HMMA/sentence. B staged directly from conv_w (prepB fused).
// Pipelined A build + deferred cross-warp epilogue. One sync per sentence.
__global__ void __launch_bounds__(NTH, 1) enc_kernel(
    const int* __restrict__ X, const int* __restrict__ pos1,
    const int* __restrict__ pos2,
    const float* __restrict__ word_emb, const float* __restrict__ p1e,
    const float* __restrict__ p2e, const float* __restrict__ conv_w,
    const float* __restrict__ conv_b)
{
    extern __shared__ char sm_raw[];
    const uint32_t raw  = smem_u32(sm_raw);
    const uint32_t base = (raw + 127u) & ~127u;
    float* scr = (float*)(sm_raw + (base - raw) + OFF_SCR);  // [2][2*240]

    const int tid  = threadIdx.x;
    const int wid  = tid >> 5;
    const int lane = tid & 31;

    // ---- stage resident B directly from conv_w (fp16 im2col, swizzled)
    for (int t = tid; t < NPC2 * KT / 4; t += NTH) {
        int idx = t * 4;
        int c = idx / KT, k = idx - c * KT;
        int tap = k >> 6, e = k & 63;
        float v0 = 0.f, v1 = 0.f, v2 = 0.f, v3 = 0.f;
        if (c < HID) {
            const float* wp = conv_w + (c * EMB + e) * 3 + tap;
            if (e     < EMB) v0 = wp[0];
            if (e + 1 < EMB) v1 = wp[3];
            if (e + 2 < EMB) v2 = wp[6];
            if (e + 3 < EMB) v3 = wp[9];
        }
        __half2 h01 = __float22half2_rn(make_float2(v0, v1));
        __half2 h23 = __float22half2_rn(make_float2(v2, v3));
        uint2 u;
        u.x = *reinterpret_cast<uint32_t*>(&h01);
        u.y = *reinterpret_cast<uint32_t*>(&h23);
        uint32_t off = (uint32_t)c * 384u
                     + (((uint32_t)k * 2u) ^ (((uint32_t)(c & 7)) << 4));
        sts64(base + OFF_B + off, u);
    }
    // ---- zero BOTH A slabs once (pads persist)
    for (int t = tid; t < 2 * 16640 / 16; t += NTH)
        sts128z(base + OFF_A0 + (uint32_t)t * 16u);
    __syncthreads();

    // ---- per-warp tiling: SMSP-balanced (15 units per SMSP)
    const int smsp = wid & 3;
    const int ms   = smsp >> 1;             // rows [64*ms, +64)
    const int half = smsp & 1;              // n-tile halves [0,15) / [15,30)
    const int r    = wid >> 2;              // rank within SMSP group
    const int nt0  = half * 15 + r * 4;
    const int ntiles = (r < 3) ? 4 : 3;

    // ldmatrix lane addressing
    const uint32_t lrow = (uint32_t)((lane & 7) + ((lane >> 3) & 1) * 8);
    const uint32_t lkb  = ((uint32_t)(lane >> 4) & 1u) * 16u;
    const uint32_t brow = (uint32_t)((lane & 7) + ((lane >> 4) & 1) * 8);
    const uint32_t bkb  = ((uint32_t)(lane >> 3) & 1u) * 16u;

    // ---- preamble: build sentence blockIdx.x into slab 0
    {
        uint2 pre[4];
        #pragma unroll
        for (int it = 0; it < 4; it++) {
            int idx = tid + it * NTH;
            if (idx < NQ)
                pre[it] = gather_quad_packed(blockIdx.x, idx,
                                             X, pos1, pos2, word_emb, p1e, p2e);
        }
        #pragma unroll
        for (int it = 0; it < 4; it++) {
            int idx = tid + it * NTH;
            if (idx < NQ) store_quad(base + OFF_A0, idx, pre[it]);
        }
    }
    __syncthreads();

    uint32_t abuf  = OFF_A0;
    int      sbuf  = 0;
    int      nprev = -1;
    for (int n = blockIdx.x; n < NS; n += GRID_ENC) {
        // ---- deferred finalize of previous sentence (overlaps this MMA)
        if (nprev >= 0 && tid < HID) {
            float* sp = scr + (sbuf ^ 1) * 2 * NPC2;
            float m  = fmaxf(sp[tid], sp[NPC2 + tid]);
            float hv = m + conv_b[tid];
            g_h[nprev * HID + tid] = hv > 0.f ? hv : 0.f;
        }

        const int nnext = n + GRID_ENC;
        const uint32_t anext = (abuf == OFF_A0) ? OFF_A1 : OFF_A0;

        // ---- stage 1: issue gathers for next sentence (latency hidden)
        uint2 pre[4];
        if (nnext < NS) {
            #pragma unroll
            for (int it = 0; it < 4; it++) {
                int idx = tid + it * NTH;
                if (idx < NQ)
                    pre[it] = gather_quad_packed(nnext, idx,
                                                 X, pos1, pos2, word_emb, p1e, p2e);
            }
        }

        // ---- stage 2: MMA on current slab
        float acc[4][4][4];
        #pragma unroll
        for (int mb = 0; mb < 4; mb++)
            #pragma unroll
            for (int nt = 0; nt < 4; nt++)
                #pragma unroll
                for (int q = 0; q < 4; q++) acc[mb][nt][q] = 0.f;

        for (int t = 0; t < 3; t++) {
            #pragma unroll
            for (int ks = 0; ks < 4; ks++) {
                uint32_t bh[2][4];
                const uint32_t kbB = (uint32_t)(t * 128 + ks * 32) + bkb;
                #pragma unroll
                for (int pp = 0; pp < 2; pp++) {
                    // (r=3, half=1: second ldsm reads 8 rows past the B
                    //  region into the A slab -- in-bounds smem, fragments
                    //  unused because mma is guarded by ntiles.)
                    uint32_t c = (uint32_t)(nt0 + 2 * pp) * 8u + brow;
                    uint32_t off = c * 384u + (kbB ^ ((c & 7u) << 4));
                    ldsm4(bh[pp][0], bh[pp][1], bh[pp][2], bh[pp][3],
                          base + OFF_B + off);
                }
                const uint32_t kbA = (uint32_t)(ks * 32) + lkb;
                #pragma unroll
                for (int mb = 0; mb < 4; mb++) {
                    uint32_t rr = (uint32_t)(ms * 64 + mb * 16 + t) + lrow;
                    uint32_t aoff = rr * 128u + (kbA ^ ((rr & 7u) << 4));
                    uint32_t ah[4];
                    ldsm4(ah[0], ah[1], ah[2], ah[3], base + abuf + aoff);
                    #pragma unroll
                    for (int nt = 0; nt < 4; nt++) {
                        if (nt < ntiles) {
                            int pp = nt >> 1, hf = (nt & 1) * 2;
                            mma16816(acc[mb][nt], ah, bh[pp][hf], bh[pp][hf + 1]);
                        }
                    }
                }
            }
        }

        // ---- stage 3: convert + store prefetched data to inactive slab
        if (nnext < NS) {
            #pragma unroll
            for (int it = 0; it < 4; it++) {
                int idx = tid + it * NTH;
                if (idx < NQ) store_quad(base + anext, idx, pre[it]);
            }
        }

        // ---- epilogue: warp-local partial max -> scr[sbuf]
        #pragma unroll
        for (int nt = 0; nt < 4; nt++) {
            if (nt < ntiles) {
                float ve = -1e30f, vo = -1e30f;
                #pragma unroll
                for (int mb = 0; mb < 4; mb++) {
                    ve = fmaxf(ve, fmaxf(acc[mb][nt][0], acc[mb][nt][2]));
                    vo = fmaxf(vo, fmaxf(acc[mb][nt][1], acc[mb][nt][3]));
                }
                #pragma unroll
                for (int o = 4; o <= 16; o <<= 1) {
                    ve = fmaxf(ve, __shfl_xor_sync(0xffffffffu, ve, o));
                    vo = fmaxf(vo, __shfl_xor_sync(0xffffffffu, vo, o));
                }
                if (lane < 4) {
                    int col = (nt0 + nt) * 8 + 2 * lane;
                    float* sp = scr + sbuf * 2 * NPC2 + ms * NPC2;
                    sp[col]     = ve;
                    sp[col + 1] = vo;
                }
            }
        }

        __syncthreads();   // A-stores + scr partials visible
        nprev = n;
        sbuf ^= 1;
        abuf  = anext;
    }

    // ---- tail finalize for the last sentence
    if (nprev >= 0 && tid < HID) {
        float* sp = scr + (sbuf ^ 1) * 2 * NPC2;
        float m  = fmaxf(sp[tid], sp[NPC2 + tid]);
        float hv = m + conv_b[tid];
        g_h[nprev * HID + tid] = hv > 0.f ? hv : 0.f;
    }
}

// ---------------- kernel 2: bag attention + classifier ----------------
__global__ void __launch_bounds__(256) bag_kernel(
    const int* __restrict__ scope, const int* __restrict__ relation,
    const float* __restrict__ rel_w, const float* __restrict__ rel_b,
    float* __restrict__ out)
{
    __shared__ float rq[HID];
    __shared__ float rep[HID];
    __shared__ float logits[64];
    __shared__ float alpha[64];

    const int b = blockIdx.x, tid = threadIdx.x;
    const int wid = tid >> 5, lane = tid & 31;
    const int s0 = scope[2 * b], s1 = scope[2 * b + 1];
    const int sz = s1 - s0;
    const int rel = relation[b];

    for (int d = tid; d < HID; d += 256) rq[d] = rel_w[rel * HID + d];
    __syncthreads();

    for (int i = wid; i < sz && i < 64; i += 8) {
        const float* hr = g_h + (s0 + i) * HID;
        float s = 0.f;
        for (int d = lane; d < HID; d += 32) s += hr[d] * rq[d];
        #pragma unroll
        for (int o = 16; o > 0; o >>= 1) s += __shfl_xor_sync(0xffffffffu, s, o);
        if (lane == 0) logits[i] = s;
    }
    __syncthreads();

    if (tid == 0) {
        float m = -1e30f;
        for (int i = 0; i < sz && i < 64; i++) m = fmaxf(m, logits[i]);
        float den = 0.f;
        for (int i = 0; i < sz && i < 64; i++) {
            float e = expf(logits[i] - m);
            alpha[i] = e; den += e;
        }
        float inv = 1.f / den;
        for (int i = 0; i < sz && i < 64; i++) alpha[i] *= inv;
    }
    __syncthreads();

    for (int d = tid; d < HID; d += 256) {
        float a = 0.f;
        for (int i = 0; i < sz && i < 64; i++)
            a += alpha[i] * g_h[(s0 + i) * HID + d];
        rep[d] = a;
    }
    __syncthreads();

    for (int r = wid; r < NREL; r += 8) {
        float s = 0.f;
        for (int d = lane; d < HID; d += 32) s += rep[d] * rel_w[r * HID + d];
        #pragma unroll
        for (int o = 16; o > 0; o >>= 1) s += __shfl_xor_sync(0xffffffffu, s, o);
        if (lane == 0) out[b * NREL + r] = s + rel_b[r];
    }
}

// ---------------------------------------------------------------------------
extern "C" void kernel_launch(void* const* d_in, const int* in_sizes, int n_in,
                              void* d_out, int out_size)
{
    const int*   X        = (const int*)d_in[0];
    const int*   pos1     = (const int*)d_in[1];
    const int*   pos2     = (const int*)d_in[2];
    const int*   scope    = (const int*)d_in[5];
    const int*   relation = (const int*)d_in[6];
    const float* word_emb = (const float*)d_in[7];
    const float* p1e      = (const float*)d_in[8];
    const float* p2e      = (const float*)d_in[9];
    const float* conv_w   = (const float*)d_in[10];
    const float* conv_b   = (const float*)d_in[11];
    const float* rel_w    = (const float*)d_in[12];
    const float* rel_b    = (const float*)d_in[13];
    float*       out      = (float*)d_out;

    cudaFuncSetAttribute(enc_kernel,
                         cudaFuncAttributeMaxDynamicSharedMemorySize, SMEM_NEED);

    enc_kernel<<<GRID_ENC, NTH, SMEM_NEED>>>(X, pos1, pos2, word_emb, p1e, p2e,
                                             conv_w, conv_b);
    bag_kernel<<<NBAG, 256>>>(scope, relation, rel_w, rel_b, out);
}

// round 17
// speedup vs baseline: 2.8855x; 1.0348x over previous
#include <cuda_runtime.h>
#include <cuda_fp16.h>
#include <math.h>
#include <stdint.h>

// ---------------- problem constants ----------------
#define NS   4000
#define SL   128
#define VEC  50
#define PDIM 5
#define EMB  60
#define HID  230
#define NBAG 500
#define NREL 25

#define NPC2 240          // channels padded to 30 n-tiles
#define KT   192          // K = 3 taps * 64
#define GRID_ENC 152      // 1 CTA per SM
#define NQ   1920         // SL * 15 e-quads
#define NTH  512

// smem offsets (base 128-aligned)
#define OFF_B    0u                       // 240*384 = 92160
#define A_SLAB(s) (92160u + (uint32_t)(s) * 16640u)   // 4 slabs of 130*128B
#define OFF_SCR  158720u                  // 2 bufs * 2 sent * 480 floats = 7680
#define SMEM_NEED (166400 + 128)

__device__ float g_h[NS * HID];

// ---------------- helpers ----------------
__device__ __forceinline__ uint32_t smem_u32(const void* p) {
    uint32_t a;
    asm("{ .reg .u64 t; cvta.to.shared.u64 t, %1; cvt.u32.u64 %0, t; }"
        : "=r"(a) : "l"(p));
    return a;
}
__device__ __forceinline__ void sts64(uint32_t a, uint2 v) {
    asm volatile("st.shared.v2.u32 [%0], {%1,%2};" :: "r"(a), "r"(v.x), "r"(v.y));
}
__device__ __forceinline__ void sts128z(uint32_t a) {
    asm volatile("st.shared.v4.u32 [%0], {%1,%1,%1,%1};" :: "r"(a), "r"(0u));
}
__device__ __forceinline__ void ldsm4(uint32_t& r0, uint32_t& r1, uint32_t& r2,
                                      uint32_t& r3, uint32_t addr) {
    asm volatile("ldmatrix.sync.aligned.m8n8.x4.shared.b16 {%0,%1,%2,%3}, [%4];"
                 : "=r"(r0), "=r"(r1), "=r"(r2), "=r"(r3) : "r"(addr));
}
__device__ __forceinline__ void mma16816(float* c, const uint32_t* a,
                                         uint32_t b0, uint32_t b1) {
    asm volatile(
        "mma.sync.aligned.m16n8k16.row.col.f32.f16.f16.f32 "
        "{%0,%1,%2,%3}, {%4,%5,%6,%7}, {%8,%9}, {%0,%1,%2,%3};"
        : "+f"(c[0]), "+f"(c[1]), "+f"(c[2]), "+f"(c[3])
        : "r"(a[0]), "r"(a[1]), "r"(a[2]), "r"(a[3]), "r"(b0), "r"(b1));
}

// gather one (l, e0..e0+3) quad of sentence n, packed to half2x2
__device__ __forceinline__ uint2 gather_quad_packed(
    int n, int idx,
    const int* __restrict__ X, const int* __restrict__ pos1,
    const int* __restrict__ pos2,
    const float* __restrict__ word_emb, const float* __restrict__ p1e,
    const float* __restrict__ p2e)
{
    int l = idx / 15, q = idx - l * 15;
    int e0 = q * 4;
    float x0, x1, x2, x3;
    if (e0 <= 44) {                              // pure word quad
        int tok = X[n * SL + l];
        float2 a = *reinterpret_cast<const float2*>(word_emb + tok * VEC + e0);
        float2 b = *reinterpret_cast<const float2*>(word_emb + tok * VEC + e0 + 2);
        x0 = a.x; x1 = a.y; x2 = b.x; x3 = b.y;
    } else if (e0 == 48) {                       // word[48,49], p1[0,1]
        int tok = X[n * SL + l];
        float2 a = *reinterpret_cast<const float2*>(word_emb + tok * VEC + 48);
        int t1 = pos1[n * SL + l];
        x0 = a.x; x1 = a.y;
        x2 = p1e[t1 * PDIM + 0]; x3 = p1e[t1 * PDIM + 1];
    } else if (e0 == 52) {                       // p1[2,3,4], p2[0]
        int t1 = pos1[n * SL + l];
        int t2 = pos2[n * SL + l];
        x0 = p1e[t1 * PDIM + 2]; x1 = p1e[t1 * PDIM + 3];
        x2 = p1e[t1 * PDIM + 4]; x3 = p2e[t2 * PDIM + 0];
    } else {                                     // e0 == 56: p2[1..4]
        int t2 = pos2[n * SL + l];
        x0 = p2e[t2 * PDIM + 1]; x1 = p2e[t2 * PDIM + 2];
        x2 = p2e[t2 * PDIM + 3]; x3 = p2e[t2 * PDIM + 4];
    }
    __half2 h01 = __float22half2_rn(make_float2(x0, x1));
    __half2 h23 = __float22half2_rn(make_float2(x2, x3));
    uint2 u;
    u.x = *reinterpret_cast<uint32_t*>(&h01);
    u.y = *reinterpret_cast<uint32_t*>(&h23);
    return u;
}

__device__ __forceinline__ void store_quad(uint32_t slab, int idx, uint2 u) {
    int l = idx / 15, q = idx - l * 15;
    uint32_t e0b = (uint32_t)(q * 8);
    uint32_t p   = (uint32_t)(l + 1);
    uint32_t off = p * 128u + (e0b ^ ((p & 7u) << 4));
    sts64(slab + off, u);
}

// ---------------- kernel 1: persistent mma.sync encoder ---------------------
// Single-term fp16; 512 threads; SMSP-balanced tiling; TWO sentences per
// loop iteration (4 A slabs, pair double-buffer) -> ONE barrier per pair.
// Deferred finalize handles both sentences in one pass (tid<230 / tid>=256).
__global__ void __launch_bounds__(NTH, 1) enc_kernel(
    const int* __restrict__ X, const int* __restrict__ pos1,
    const int* __restrict__ pos2,
    const float* __restrict__ word_emb, const float* __restrict__ p1e,
    const float* __restrict__ p2e, const float* __restrict__ conv_w,
    const float* __restrict__ conv_b)
{
    extern __shared__ char sm_raw[];
    const uint32_t raw  = smem_u32(sm_raw);
    const uint32_t base = (raw + 127u) & ~127u;
    float* scr = (float*)(sm_raw + (base - raw) + OFF_SCR);  // [2][2][480]

    const int tid  = threadIdx.x;
    const int wid  = tid >> 5;
    const int lane = tid & 31;

    // ---- stage resident B directly from conv_w (fp16 im2col, swizzled)
    for (int t = tid; t < NPC2 * KT / 4; t += NTH) {
        int idx = t * 4;
        int c = idx / KT, k = idx - c * KT;
        int tap = k >> 6, e = k & 63;
        float v0 = 0.f, v1 = 0.f, v2 = 0.f, v3 = 0.f;
        if (c < HID) {
            const float* wp = conv_w + (c * EMB + e) * 3 + tap;
            if (e     < EMB) v0 = wp[0];
            if (e + 1 < EMB) v1 = wp[3];
            if (e + 2 < EMB) v2 = wp[6];
            if (e + 3 < EMB) v3 = wp[9];
        }
        __half2 h01 = __float22half2_rn(make_float2(v0, v1));
        __half2 h23 = __float22half2_rn(make_float2(v2, v3));
        uint2 u;
        u.x = *reinterpret_cast<uint32_t*>(&h01);
        u.y = *reinterpret_cast<uint32_t*>(&h23);
        uint32_t off = (uint32_t)c * 384u
                     + (((uint32_t)k * 2u) ^ (((uint32_t)(c & 7)) << 4));
        sts64(base + OFF_B + off, u);
    }
    // ---- zero ALL FOUR A slabs once (pads persist)
    for (int t = tid; t < 4 * 16640 / 16; t += NTH)
        sts128z(A_SLAB(0) + base + (uint32_t)t * 16u);
    __syncthreads();

    // ---- per-warp tiling: SMSP-balanced (15 units per SMSP)
    const int smsp = wid & 3;
    const int ms   = smsp >> 1;             // rows [64*ms, +64)
    const int half = smsp & 1;              // n-tile halves [0,15) / [15,30)
    const int r    = wid >> 2;              // rank within SMSP group
    const int nt0  = half * 15 + r * 4;
    const int ntiles = (r < 3) ? 4 : 3;

    // ldmatrix lane addressing
    const uint32_t lrow = (uint32_t)((lane & 7) + ((lane >> 3) & 1) * 8);
    const uint32_t lkb  = ((uint32_t)(lane >> 4) & 1u) * 16u;
    const uint32_t brow = (uint32_t)((lane & 7) + ((lane >> 4) & 1) * 8);
    const uint32_t bkb  = ((uint32_t)(lane >> 3) & 1u) * 16u;

    // ---- preamble: build first pair (b, b+152) into slabs 0,1
    {
        uint2 pre[4];
        #pragma unroll
        for (int it = 0; it < 4; it++) {
            int idx = tid + it * NTH;
            if (idx < NQ)
                pre[it] = gather_quad_packed(blockIdx.x, idx,
                                             X, pos1, pos2, word_emb, p1e, p2e);
        }
        #pragma unroll
        for (int it = 0; it < 4; it++) {
            int idx = tid + it * NTH;
            if (idx < NQ) store_quad(base + A_SLAB(0), idx, pre[it]);
        }
        int n1 = blockIdx.x + GRID_ENC;
        if (n1 < NS) {
            #pragma unroll
            for (int it = 0; it < 4; it++) {
                int idx = tid + it * NTH;
                if (idx < NQ)
                    pre[it] = gather_quad_packed(n1, idx,
                                                 X, pos1, pos2, word_emb, p1e, p2e);
            }
            #pragma unroll
            for (int it = 0; it < 4; it++) {
                int idx = tid + it * NTH;
                if (idx < NQ) store_quad(base + A_SLAB(1), idx, pre[it]);
            }
        }
    }
    __syncthreads();

    int pairbuf = 0;   // slabs {2*pairbuf, 2*pairbuf+1} hold current pair
    int sbuf    = 0;
    int nprev0  = -1, nprev1 = -1;
    for (int n0 = blockIdx.x; n0 < NS; n0 += 2 * GRID_ENC) {
        const int n1  = n0 + GRID_ENC;
        const int nn0 = n0 + 2 * GRID_ENC;
        const int nn1 = nn0 + GRID_ENC;
        const uint32_t curA0 = base + A_SLAB(2 * pairbuf);
        const uint32_t curA1 = base + A_SLAB(2 * pairbuf + 1);
        const uint32_t nxtA0 = base + A_SLAB(2 * (pairbuf ^ 1));
        const uint32_t nxtA1 = base + A_SLAB(2 * (pairbuf ^ 1) + 1);

        // ---- deferred finalize of previous pair (overlaps this MMA)
        {
            float* sp = scr + (sbuf ^ 1) * 2 * 2 * NPC2;
            if (nprev0 >= 0 && tid < HID) {
                float m  = fmaxf(sp[tid], sp[NPC2 + tid]);
                float hv = m + conv_b[tid];
                g_h[nprev0 * HID + tid] = hv > 0.f ? hv : 0.f;
            }
            if (nprev1 >= 0 && tid >= 256 && tid < 256 + HID) {
                int d = tid - 256;
                float m  = fmaxf(sp[2 * NPC2 + d], sp[3 * NPC2 + d]);
                float hv = m + conv_b[d];
                g_h[nprev1 * HID + d] = hv > 0.f ? hv : 0.f;
            }
        }

        // ================= sentence 0 of the pair =================
        uint2 pre[4];
        if (nn0 < NS) {
            #pragma unroll
            for (int it = 0; it < 4; it++) {
                int idx = tid + it * NTH;
                if (idx < NQ)
                    pre[it] = gather_quad_packed(nn0, idx,
                                                 X, pos1, pos2, word_emb, p1e, p2e);
            }
        }
        {
            float acc[4][4][4];
            #pragma unroll
            for (int mb = 0; mb < 4; mb++)
                #pragma unroll
                for (int nt = 0; nt < 4; nt++)
                    #pragma unroll
                    for (int q = 0; q < 4; q++) acc[mb][nt][q] = 0.f;

            for (int t = 0; t < 3; t++) {
                #pragma unroll
                for (int ks = 0; ks < 4; ks++) {
                    uint32_t bh[2][4];
                    const uint32_t kbB = (uint32_t)(t * 128 + ks * 32) + bkb;
                    #pragma unroll
                    for (int pp = 0; pp < 2; pp++) {
                        uint32_t c = (uint32_t)(nt0 + 2 * pp) * 8u + brow;
                        uint32_t off = c * 384u + (kbB ^ ((c & 7u) << 4));
                        ldsm4(bh[pp][0], bh[pp][1], bh[pp][2], bh[pp][3],
                              base + OFF_B + off);
                    }
                    const uint32_t kbA = (uint32_t)(ks * 32) + lkb;
                    #pragma unroll
                    for (int mb = 0; mb < 4; mb++) {
                        uint32_t rr = (uint32_t)(ms * 64 + mb * 16 + t) + lrow;
                        uint32_t aoff = rr * 128u + (kbA ^ ((rr & 7u) << 4));
                        uint32_t ah[4];
                        ldsm4(ah[0], ah[1], ah[2], ah[3], curA0 + aoff);
                        #pragma unroll
                        for (int nt = 0; nt < 4; nt++) {
                            if (nt < ntiles) {
                                int pp = nt >> 1, hf = (nt & 1) * 2;
                                mma16816(acc[mb][nt], ah, bh[pp][hf], bh[pp][hf + 1]);
                            }
                        }
                    }
                }
            }
            #pragma unroll
            for (int nt = 0; nt < 4; nt++) {
                if (nt < ntiles) {
                    float ve = -1e30f, vo = -1e30f;
                    #pragma unroll
                    for (int mb = 0; mb < 4; mb++) {
                        ve = fmaxf(ve, fmaxf(acc[mb][nt][0], acc[mb][nt][2]));
                        vo = fmaxf(vo, fmaxf(acc[mb][nt][1], acc[mb][nt][3]));
                    }
                    #pragma unroll
                    for (int o = 4; o <= 16; o <<= 1) {
                        ve = fmaxf(ve, __shfl_xor_sync(0xffffffffu, ve, o));
                        vo = fmaxf(vo, __shfl_xor_sync(0xffffffffu, vo, o));
                    }
                    if (lane < 4) {
                        int col = (nt0 + nt) * 8 + 2 * lane;
                        float* sp = scr + sbuf * 2 * 2 * NPC2 + ms * NPC2;
                        sp[col]     = ve;
                        sp[col + 1] = vo;
                    }
                }
            }
        }
        if (nn0 < NS) {
            #pragma unroll
            for (int it = 0; it < 4; it++) {
                int idx = tid + it * NTH;
                if (idx < NQ) store_quad(nxtA0, idx, pre[it]);
            }
        }

        // ================= sentence 1 of the pair =================
        if (n1 < NS) {
            if (nn1 < NS) {
                #pragma unroll
                for (int it = 0; it < 4; it++) {
                    int idx = tid + it * NTH;
                    if (idx < NQ)
                        pre[it] = gather_quad_packed(nn1, idx,
                                                     X, pos1, pos2, word_emb, p1e, p2e);
                }
            }
            float acc[4][4][4];
            #pragma unroll
            for (int mb = 0; mb < 4; mb++)
                #pragma unroll
                for (int nt = 0; nt < 4; nt++)
                    #pragma unroll
                    for (int q = 0; q < 4; q++) acc[mb][nt][q] = 0.f;

            for (int t = 0; t < 3; t++) {
                #pragma unroll
                for (int ks = 0; ks < 4; ks++) {
                    uint32_t bh[2][4];
                    const uint32_t kbB = (uint32_t)(t * 128 + ks * 32) + bkb;
                    #pragma unroll
                    for (int pp = 0; pp < 2; pp++) {
                        uint32_t c = (uint32_t)(nt0 + 2 * pp) * 8u + brow;
                        uint32_t off = c * 384u + (kbB ^ ((c & 7u) << 4));
                        ldsm4(bh[pp][0], bh[pp][1], bh[pp][2], bh[pp][3],
                              base + OFF_B + off);
                    }
                    const uint32_t kbA = (uint32_t)(ks * 32) + lkb;
                    #pragma unroll
                    for (int mb = 0; mb < 4; mb++) {
                        uint32_t rr = (uint32_t)(ms * 64 + mb * 16 + t) + lrow;
                        uint32_t aoff = rr * 128u + (kbA ^ ((rr & 7u) << 4));
                        uint32_t ah[4];
                        ldsm4(ah[0], ah[1], ah[2], ah[3], curA1 + aoff);
                        #pragma unroll
                        for (int nt = 0; nt < 4; nt++) {
                            if (nt < ntiles) {
                                int pp = nt >> 1, hf = (nt & 1) * 2;
                                mma16816(acc[mb][nt], ah, bh[pp][hf], bh[pp][hf + 1]);
                            }
                        }
                    }
                }
            }
            #pragma unroll
            for (int nt = 0; nt < 4; nt++) {
                if (nt < ntiles) {
                    float ve = -1e30f, vo = -1e30f;
                    #pragma unroll
                    for (int mb = 0; mb < 4; mb++) {
                        ve = fmaxf(ve, fmaxf(acc[mb][nt][0], acc[mb][nt][2]));
                        vo = fmaxf(vo, fmaxf(acc[mb][nt][1], acc[mb][nt][3]));
                    }
                    #pragma unroll
                    for (int o = 4; o <= 16; o <<= 1) {
                        ve = fmaxf(ve, __shfl_xor_sync(0xffffffffu, ve, o));
                        vo = fmaxf(vo, __shfl_xor_sync(0xffffffffu, vo, o));
                    }
                    if (lane < 4) {
                        int col = (nt0 + nt) * 8 + 2 * lane;
                        float* sp = scr + sbuf * 2 * 2 * NPC2 + 2 * NPC2 + ms * NPC2;
                        sp[col]     = ve;
                        sp[col + 1] = vo;
                    }
                }
            }
            if (nn1 < NS) {
                #pragma unroll
                for (int it = 0; it < 4; it++) {
                    int idx = tid + it * NTH;
                    if (idx < NQ) store_quad(nxtA1, idx, pre[it]);
                }
            }
        }

        __syncthreads();   // A-stores + both scr partial sets visible
        nprev0 = n0;
        nprev1 = (n1 < NS) ? n1 : -1;
        sbuf   ^= 1;
        pairbuf ^= 1;
    }

    // ---- tail finalize for the last pair
    {
        float* sp = scr + (sbuf ^ 1) * 2 * 2 * NPC2;
        if (nprev0 >= 0 && tid < HID) {
            float m  = fmaxf(sp[tid], sp[NPC2 + tid]);
            float hv = m + conv_b[tid];
            g_h[nprev0 * HID + tid] = hv > 0.f ? hv : 0.f;
        }
        if (nprev1 >= 0 && tid >= 256 && tid < 256 + HID) {
            int d = tid - 256;
            float m  = fmaxf(sp[2 * NPC2 + d], sp[3 * NPC2 + d]);
            float hv = m + conv_b[d];
            g_h[nprev1 * HID + d] = hv > 0.f ? hv : 0.f;
        }
    }
}

// ---------------- kernel 2: bag attention + classifier ----------------
__global__ void __launch_bounds__(256) bag_kernel(
    const int* __restrict__ scope, const int* __restrict__ relation,
    const float* __restrict__ rel_w, const float* __restrict__ rel_b,
    float* __restrict__ out)
{
    __shared__ float rq[HID];
    __shared__ float rep[HID];
    __shared__ float logits[64];
    __shared__ float alpha[64];

    const int b = blockIdx.x, tid = threadIdx.x;
    const int wid = tid >> 5, lane = tid & 31;
    const int s0 = scope[2 * b], s1 = scope[2 * b + 1];
    const int sz = s1 - s0;
    const int rel = relation[b];

    for (int d = tid; d < HID; d += 256) rq[d] = rel_w[rel * HID + d];
    __syncthreads();

    for (int i = wid; i < sz && i < 64; i += 8) {
        const float* hr = g_h + (s0 + i) * HID;
        float s = 0.f;
        for (int d = lane; d < HID; d += 32) s += hr[d] * rq[d];
        #pragma unroll
        for (int o = 16; o > 0; o >>= 1) s += __shfl_xor_sync(0xffffffffu, s, o);
        if (lane == 0) logits[i] = s;
    }
    __syncthreads();

    if (tid == 0) {
        float m = -1e30f;
        for (int i = 0; i < sz && i < 64; i++) m = fmaxf(m, logits[i]);
        float den = 0.f;
        for (int i = 0; i < sz && i < 64; i++) {
            float e = expf(logits[i] - m);
            alpha[i] = e; den += e;
        }
        float inv = 1.f / den;
        for (int i = 0; i < sz && i < 64; i++) alpha[i] *= inv;
    }
    __syncthreads();

    for (int d = tid; d < HID; d += 256) {
        float a = 0.f;
        for (int i = 0; i < sz && i < 64; i++)
            a += alpha[i] * g_h[(s0 + i) * HID + d];
        rep[d] = a;
    }
    __syncthreads();

    for (int r = wid; r < NREL; r += 8) {
        float s = 0.f;
        for (int d = lane; d < HID; d += 32) s += rep[d] * rel_w[r * HID + d];
        #pragma unroll
        for (int o = 16; o > 0; o >>= 1) s += __shfl_xor_sync(0xffffffffu, s, o);
        if (lane == 0) out[b * NREL + r] = s + rel_b[r];
    }
}

// ---------------------------------------------------------------------------
extern "C" void kernel_launch(void* const* d_in, const int* in_sizes, int n_in,
                              void* d_out, int out_size)
{
    const int*   X        = (const int*)d_in[0];
    const int*   pos1     = (const int*)d_in[1];
    const int*   pos2     = (const int*)d_in[2];
    const int*   scope    = (const int*)d_in[5];
    const int*   relation = (const int*)d_in[6];
    const float* word_emb = (const float*)d_in[7];
    const float* p1e      = (const float*)d_in[8];
    const float* p2e      = (const float*)d_in[9];
    const float* conv_w   = (const float*)d_in[10];
    const float* conv_b   = (const float*)d_in[11];
    const float* rel_w    = (const float*)d_in[12];
    const float* rel_b    = (const float*)d_in[13];
    float*       out      = (float*)d_out;

    cudaFuncSetAttribute(enc_kernel,
                         cudaFuncAttributeMaxDynamicSharedMemorySize, SMEM_NEED);

    enc_kernel<<<GRID_ENC, NTH, SMEM_NEED>>>(X, pos1, pos2, word_emb, p1e, p2e,
                                             conv_w, conv_b);
    bag_kernel<<<NBAG, 256>>>(scope, relation, rel_w, rel_b, out);
}